// round 4
// baseline (speedup 1.0000x reference)
#include <cuda_runtime.h>
#include <math.h>
#include <stdint.h>

#define NN    50000
#define NE    320000
#define D_IN  128
#define D_OUT 256
#define D_HID 512

// ---------------- scratch (static device globals; no allocation) ----------------
__device__ float  g_X1 [(size_t)NN * D_IN];
__device__ float  g_XN [(size_t)NN * D_OUT];
__device__ float  g_H  [(size_t)NN * D_OUT];
__device__ float  g_T  [(size_t)NN * D_HID];
__device__ float  g_U  [(size_t)NN * D_OUT];
__device__ float  g_RE1[(size_t)NN * D_IN];
__device__ float  g_RE2[(size_t)NN * D_IN];
__device__ double g_sum[D_HID];
__device__ double g_sq [D_HID];
__device__ float  g_mean[D_HID];
__device__ float  g_rstd[D_HID];
__device__ double g_acc[8]; // [0]=sum1 [1]=cnt1 [2]=sum2 [3]=cnt2 [4]=cl_sum

// dtype-detection flags + counters
__device__ int g_mask_mode;   // 0 = uint8, 1 = int32, 2 = float32
__device__ int g_ei_i64;      // 0 = int32, 1 = int64
__device__ int g_cnt[8];

// ---------------- dtype detection ----------------
__global__ void k_zero_cnt() { if (threadIdx.x < 8) g_cnt[threadIdx.x] = 0; }

__global__ void k_detect(const unsigned char* __restrict__ mbytes,
                         const int* __restrict__ eints) {
    int i  = blockIdx.x * blockDim.x + threadIdx.x;
    int st = gridDim.x * blockDim.x;
    int c1 = 0, c3 = 0, ez = 0;
    for (int j = i; j < NN; j += st) {
        unsigned char v = mbytes[j];
        if (v && (j & 3) == 1) c1++;
        if (v && (j & 3) == 3) c3++;
    }
    for (int j = i; j < 100000; j += st)
        if ((j & 1) && eints[j] == 0) ez++;
    atomicAdd(&g_cnt[0], c1);
    atomicAdd(&g_cnt[1], c3);
    atomicAdd(&g_cnt[2], ez);
}

__global__ void k_detect_fin() {
    if (threadIdx.x == 0) {
        if      (g_cnt[1] > 1000) g_mask_mode = 2;
        else if (g_cnt[0] > 1000) g_mask_mode = 0;
        else                      g_mask_mode = 1;
        g_ei_i64 = (g_cnt[2] > 25000) ? 1 : 0;
    }
}

__device__ __forceinline__ bool mask_at(const void* __restrict__ m, int n) {
    int mode = g_mask_mode;
    if (mode == 0) return ((const unsigned char*)m)[n] != 0;
    if (mode == 1) return ((const int*)m)[n] != 0;
    return ((const float*)m)[n] != 0.f;
}

__device__ __forceinline__ int ei_at(const void* __restrict__ ei, long idx) {
    return g_ei_i64 ? (int)((const long long*)ei)[idx] : ((const int*)ei)[idx];
}

// ---------------- tiny utility kernels ----------------
__global__ void k_zero_acc() {
    if (threadIdx.x < 8) g_acc[threadIdx.x] = 0.0;
    // also zero stat accumulators once at start
    int c = blockIdx.x * blockDim.x + threadIdx.x;
    if (c < D_HID) { g_sum[c] = 0.0; g_sq[c] = 0.0; }
}

// mask + dual write: out[i] = H[i] = mask[node] ? 0 : in[i]
__global__ void k_mask_dual(const float* __restrict__ in, const void* __restrict__ m,
                            float* __restrict__ out, float* __restrict__ h,
                            int dshift, long total) {
    long i  = blockIdx.x * (long)blockDim.x + threadIdx.x;
    long st = (long)gridDim.x * blockDim.x;
    for (; i < total; i += st) {
        int node = (int)(i >> dshift);
        float v  = mask_at(m, node) ? 0.f : in[i];
        out[i] = v;
        h[i]   = v;
    }
}

// ---------------- edge scatter: h[dst] += xn[src], one warp per edge ----------------
__global__ void k_scatter(const float* __restrict__ xn, float* __restrict__ h,
                          const void* __restrict__ ei, int D) {
    int gtid = blockIdx.x * blockDim.x + threadIdx.x;
    int warp = gtid >> 5, lane = gtid & 31;
    int nw   = (gridDim.x * blockDim.x) >> 5;
    int D4   = D >> 2;
    for (int e = warp; e < NE; e += nw) {
        int s = ei_at(ei, e);
        int d = ei_at(ei, (long)NE + e);
        const float4* sp = (const float4*)(xn + (size_t)s * D);
        float*        dp = h + (size_t)d * D;
        for (int c = lane; c < D4; c += 32) {
            float4 v = __ldg(&sp[c]);
            atomicAdd(&dp[c * 4 + 0], v.x);
            atomicAdd(&dp[c * 4 + 1], v.y);
            atomicAdd(&dp[c * 4 + 2], v.z);
            atomicAdd(&dp[c * 4 + 3], v.w);
        }
    }
}

// ---------------- TF32 tensor-core GEMM with fused BN ----------------
// C[MxN] = act(A)[MxK] @ B[KxN]; act = identity (BNA=0) or relu(bn(.)) (BNA=1,
// using g_mean/g_rstd + gg/bb indexed by A-column). Epilogue accumulates
// per-column sum / sumsq of C into g_sum / g_sq (double atomics).
__device__ __forceinline__ uint32_t f2tf32(float f) {
    uint32_t r;
    asm("cvt.rna.tf32.f32 %0, %1;" : "=r"(r) : "f"(f));
    return r;
}

__device__ __forceinline__ void mma_tf32(float* d, const uint32_t* a, const uint32_t* b) {
    asm volatile(
        "mma.sync.aligned.m16n8k8.row.col.f32.tf32.tf32.f32 "
        "{%0,%1,%2,%3}, {%4,%5,%6,%7}, {%8,%9}, {%0,%1,%2,%3};"
        : "+f"(d[0]), "+f"(d[1]), "+f"(d[2]), "+f"(d[3])
        : "r"(a[0]), "r"(a[1]), "r"(a[2]), "r"(a[3]), "r"(b[0]), "r"(b[1]));
}

template <bool BNA>
__global__ void __launch_bounds__(256)
k_gemm(const float* __restrict__ A, const float* __restrict__ B,
       float* __restrict__ C,
       const float* __restrict__ gg, const float* __restrict__ bb,
       int M, int K, int N) {
    __shared__ uint32_t As[128][20];
    __shared__ uint32_t Bs[16][136];
    __shared__ float s_sum[128], s_sq[128];

    const int tid  = threadIdx.x;
    const int lane = tid & 31;
    const int warp = tid >> 5;
    const int wm   = warp & 3;
    const int wn   = warp >> 2;
    const int gid  = lane >> 2;
    const int tq   = lane & 3;
    const int brow = blockIdx.y * 128;
    const int bcol = blockIdx.x * 128;

    float acc[2][8][4];
    #pragma unroll
    for (int i = 0; i < 2; i++)
        #pragma unroll
        for (int j = 0; j < 8; j++)
            #pragma unroll
            for (int q = 0; q < 4; q++) acc[i][j][q] = 0.f;

    for (int k0 = 0; k0 < K; k0 += 16) {
        #pragma unroll
        for (int i = 0; i < 2; i++) {
            int idx = tid + i * 256;
            int row = idx >> 2;
            int c4  = (idx & 3) << 2;
            float4 v = make_float4(0.f, 0.f, 0.f, 0.f);
            if (brow + row < M) {
                v = *(const float4*)(A + (size_t)(brow + row) * K + k0 + c4);
                if (BNA) {
                    int ch = k0 + c4;
                    v.x = fmaxf((v.x - g_mean[ch + 0]) * g_rstd[ch + 0] * __ldg(&gg[ch + 0]) + __ldg(&bb[ch + 0]), 0.f);
                    v.y = fmaxf((v.y - g_mean[ch + 1]) * g_rstd[ch + 1] * __ldg(&gg[ch + 1]) + __ldg(&bb[ch + 1]), 0.f);
                    v.z = fmaxf((v.z - g_mean[ch + 2]) * g_rstd[ch + 2] * __ldg(&gg[ch + 2]) + __ldg(&bb[ch + 2]), 0.f);
                    v.w = fmaxf((v.w - g_mean[ch + 3]) * g_rstd[ch + 3] * __ldg(&gg[ch + 3]) + __ldg(&bb[ch + 3]), 0.f);
                }
            }
            As[row][c4 + 0] = f2tf32(v.x);
            As[row][c4 + 1] = f2tf32(v.y);
            As[row][c4 + 2] = f2tf32(v.z);
            As[row][c4 + 3] = f2tf32(v.w);
        }
        #pragma unroll
        for (int i = 0; i < 2; i++) {
            int idx = tid + i * 256;
            int kr = idx >> 5;
            int nc = (idx & 31) << 2;
            float4 v = *(const float4*)(B + (size_t)(k0 + kr) * N + bcol + nc);
            Bs[kr][nc + 0] = f2tf32(v.x);
            Bs[kr][nc + 1] = f2tf32(v.y);
            Bs[kr][nc + 2] = f2tf32(v.z);
            Bs[kr][nc + 3] = f2tf32(v.w);
        }
        __syncthreads();

        #pragma unroll
        for (int kk = 0; kk < 16; kk += 8) {
            uint32_t a[2][4], b[8][2];
            #pragma unroll
            for (int mt = 0; mt < 2; mt++) {
                int r = wm * 32 + mt * 16 + gid;
                a[mt][0] = As[r][kk + tq];
                a[mt][1] = As[r + 8][kk + tq];
                a[mt][2] = As[r][kk + tq + 4];
                a[mt][3] = As[r + 8][kk + tq + 4];
            }
            #pragma unroll
            for (int nt = 0; nt < 8; nt++) {
                int cn = wn * 64 + nt * 8 + gid;
                b[nt][0] = Bs[kk + tq][cn];
                b[nt][1] = Bs[kk + tq + 4][cn];
            }
            #pragma unroll
            for (int mt = 0; mt < 2; mt++)
                #pragma unroll
                for (int nt = 0; nt < 8; nt++)
                    mma_tf32(acc[mt][nt], a[mt], b[nt]);
        }
        __syncthreads();
    }

    // store C + per-column stats reduction
    if (tid < 128) { s_sum[tid] = 0.f; s_sq[tid] = 0.f; }
    __syncthreads();

    #pragma unroll
    for (int mt = 0; mt < 2; mt++) {
        int r0 = brow + wm * 32 + mt * 16 + gid;
        int r1 = r0 + 8;
        #pragma unroll
        for (int nt = 0; nt < 8; nt++) {
            int lc = wn * 64 + nt * 8 + tq * 2;
            int c  = bcol + lc;
            float v0 = acc[mt][nt][0], v1 = acc[mt][nt][1];
            float v2 = acc[mt][nt][2], v3 = acc[mt][nt][3];
            if (r0 < M) {
                *(float2*)(C + (size_t)r0 * N + c) = make_float2(v0, v1);
                atomicAdd(&s_sum[lc],     v0);
                atomicAdd(&s_sum[lc + 1], v1);
                atomicAdd(&s_sq[lc],      v0 * v0);
                atomicAdd(&s_sq[lc + 1],  v1 * v1);
            }
            if (r1 < M) {
                *(float2*)(C + (size_t)r1 * N + c) = make_float2(v2, v3);
                atomicAdd(&s_sum[lc],     v2);
                atomicAdd(&s_sum[lc + 1], v3);
                atomicAdd(&s_sq[lc],      v2 * v2);
                atomicAdd(&s_sq[lc + 1],  v3 * v3);
            }
        }
    }
    __syncthreads();
    if (tid < 128) {
        atomicAdd(&g_sum[bcol + tid], (double)s_sum[tid]);
        atomicAdd(&g_sq[bcol + tid],  (double)s_sq[tid]);
    }
}

// mean/rstd from accumulated stats, then reset accumulators for the next GEMM
__global__ void k_bn_fin(int C) {
    int c = threadIdx.x;
    if (c < C) {
        double mu  = g_sum[c] / NN;
        double var = g_sq[c] / NN - mu * mu;
        if (var < 0.0) var = 0.0;
        g_mean[c] = (float)mu;
        g_rstd[c] = (float)rsqrt(var + 1e-5);
    }
    if (c < D_HID) { g_sum[c] = 0.0; g_sq[c] = 0.0; }
}

// out = relu(bn(in)); optionally also write a second copy (next layer's H)
__global__ void k_bn_apply_dual(const float* __restrict__ in, float* __restrict__ out,
                                float* __restrict__ h,
                                const float* __restrict__ gg, const float* __restrict__ bb,
                                int cmask, long total) {
    long i  = blockIdx.x * (long)blockDim.x + threadIdx.x;
    long st = (long)gridDim.x * blockDim.x;
    for (; i < total; i += st) {
        int c   = (int)(i & cmask);
        float v = (in[i] - g_mean[c]) * g_rstd[c] * __ldg(&gg[c]) + __ldg(&bb[c]);
        v = v > 0.f ? v : 0.f;
        out[i] = v;
        if (h) h[i] = v;
    }
}

// ---------------- cosine losses (D = 128, one warp per node) ----------------
__global__ void k_cos(const float* __restrict__ a, const float* __restrict__ b,
                      const void* __restrict__ m, int useMask, int accOff) {
    int gtid = blockIdx.x * blockDim.x + threadIdx.x;
    int warp = gtid >> 5, lane = gtid & 31;
    int nw   = (gridDim.x * blockDim.x) >> 5;
    double ls = 0.0, lc = 0.0;
    for (int n = warp; n < NN; n += nw) {
        if (useMask && !mask_at(m, n)) continue;
        float4 va = *((const float4*)(a + (size_t)n * 128) + lane);
        float4 vb = *((const float4*)(b + (size_t)n * 128) + lane);
        float dot = va.x * vb.x + va.y * vb.y + va.z * vb.z + va.w * vb.w;
        float na  = va.x * va.x + va.y * va.y + va.z * va.z + va.w * va.w;
        float nb  = vb.x * vb.x + vb.y * vb.y + vb.z * vb.z + vb.w * vb.w;
        #pragma unroll
        for (int o = 16; o; o >>= 1) {
            dot += __shfl_xor_sync(0xffffffffu, dot, o);
            na  += __shfl_xor_sync(0xffffffffu, na,  o);
            nb  += __shfl_xor_sync(0xffffffffu, nb,  o);
        }
        if (lane == 0) {
            float cs = dot / (fmaxf(sqrtf(na), 1e-12f) * fmaxf(sqrtf(nb), 1e-12f));
            ls += 1.0 - (double)cs;
            lc += 1.0;
        }
    }
    if (lane == 0) {
        atomicAdd(&g_acc[accOff], ls);
        if (useMask) atomicAdd(&g_acc[accOff + 1], lc);
    }
}

__global__ void k_finalize(float* out) {
    double v = g_acc[0] / g_acc[1] + g_acc[2] / g_acc[3] + 0.1 * (g_acc[4] / (double)NN);
    out[0] = (float)v;
}

// ---------------- host-side orchestration ----------------
// Precondition: g_sum/g_sq zeroed; H == in (scatter base preloaded).
// Postcondition: outbuf = layer output; hnext (if non-null) = layer output copy.
static void run_layer(const float* in, int din, const void* ei,
                      const float* w1, const float* w2,
                      const float* bg, const float* bb,
                      const float* ng, const float* nb,
                      int dout, float* outbuf, float* hnext,
                      float* H, float* T, float* U) {
    k_scatter<<<40000, 256>>>(in, H, ei, din);

    dim3 g1(D_HID / 128, (NN + 127) / 128);
    k_gemm<false><<<g1, 256>>>(H, w1, T, nullptr, nullptr, NN, din, D_HID);
    k_bn_fin<<<1, D_HID>>>(D_HID);

    dim3 g2(dout / 128, (NN + 127) / 128);
    k_gemm<true><<<g2, 256>>>(T, w2, U, bg, bb, NN, D_HID, dout);
    k_bn_fin<<<1, D_HID>>>(dout);

    k_bn_apply_dual<<<8192, 256>>>(U, outbuf, hnext, ng, nb, dout - 1, (long)NN * dout);
}

extern "C" void kernel_launch(void* const* d_in, const int* in_sizes, int n_in,
                              void* d_out, int out_size) {
    const float* x   = (const float*)d_in[0];
    const void*  ei1 = d_in[1];
    const void*  ei2 = d_in[2];
    const void*  m1  = d_in[3];
    const void*  m2  = d_in[4];
    // d_in[5] = batch : dead code in the reference
    const float* e0_w1 = (const float*)d_in[6];
    const float* e0_w2 = (const float*)d_in[7];
    const float* e0_bg = (const float*)d_in[8];
    const float* e0_bb = (const float*)d_in[9];
    const float* e0_ng = (const float*)d_in[10];
    const float* e0_nb = (const float*)d_in[11];
    const float* e1_w1 = (const float*)d_in[12];
    const float* e1_w2 = (const float*)d_in[13];
    const float* e1_bg = (const float*)d_in[14];
    const float* e1_bb = (const float*)d_in[15];
    const float* e1_ng = (const float*)d_in[16];
    const float* e1_nb = (const float*)d_in[17];
    const float* d_w1  = (const float*)d_in[18];
    const float* d_w2  = (const float*)d_in[19];
    const float* d_bg  = (const float*)d_in[20];
    const float* d_bb  = (const float*)d_in[21];
    const float* d_ng  = (const float*)d_in[22];
    const float* d_nb  = (const float*)d_in[23];
    float* out = (float*)d_out;

    float *X1, *XN, *H, *T, *U, *RE1, *RE2;
    cudaGetSymbolAddress((void**)&X1,  g_X1);
    cudaGetSymbolAddress((void**)&XN,  g_XN);
    cudaGetSymbolAddress((void**)&H,   g_H);
    cudaGetSymbolAddress((void**)&T,   g_T);
    cudaGetSymbolAddress((void**)&U,   g_U);
    cudaGetSymbolAddress((void**)&RE1, g_RE1);
    cudaGetSymbolAddress((void**)&RE2, g_RE2);

    // dtype auto-detection
    k_zero_cnt<<<1, 32>>>();
    k_detect<<<128, 256>>>((const unsigned char*)m1, (const int*)ei1);
    k_detect_fin<<<1, 32>>>();

    k_zero_acc<<<2, 256>>>();   // loss accumulators + stat accumulators

    for (int pass = 0; pass < 2; pass++) {
        const void* ei = pass == 0 ? ei1 : ei2;
        const void* m  = pass == 0 ? m1  : m2;
        float*      RE = pass == 0 ? RE1 : RE2;

        // x1 = where(mask,0,x); also preload scatter base H
        k_mask_dual<<<8192, 256>>>(x, m, X1, H, 7, (long)NN * D_IN);

        // encoder layer 0: 128 -> 256 (also preloads next H)
        run_layer(X1, D_IN, ei, e0_w1, e0_w2, e0_bg, e0_bb, e0_ng, e0_nb,
                  D_OUT, XN, H, H, T, U);
        // encoder layer 1: 256 -> 256
        run_layer(XN, D_OUT, ei, e1_w1, e1_w2, e1_bg, e1_bb, e1_ng, e1_nb,
                  D_OUT, XN, nullptr, H, T, U);

        // re_h = where(mask,0,h); preload decoder scatter base H
        k_mask_dual<<<8192, 256>>>(XN, m, XN, H, 8, (long)NN * D_OUT);

        // decoder layer: 256 -> 128
        run_layer(XN, D_OUT, ei, d_w1, d_w2, d_bg, d_bb, d_ng, d_nb,
                  D_IN, RE, nullptr, H, T, U);

        // masked reconstruction loss
        k_cos<<<512, 256>>>(RE, x, m, 1, pass * 2);
    }

    // contrastive term over all nodes
    k_cos<<<512, 256>>>(RE2, RE1, nullptr, 0, 4);
    k_finalize<<<1, 1>>>(out);
    (void)in_sizes; (void)n_in; (void)out_size;
}

// round 5
// speedup vs baseline: 2.5884x; 2.5884x over previous
#include <cuda_runtime.h>
#include <math.h>
#include <stdint.h>

#define NN    50000
#define NE    320000
#define D_IN  128
#define D_OUT 256
#define D_HID 512

// ---------------- scratch (static device globals; no allocation) ----------------
__device__ float  g_X1 [(size_t)NN * D_IN];
__device__ float  g_XN [(size_t)NN * D_OUT];
__device__ float  g_H  [(size_t)NN * D_OUT];
__device__ float  g_T  [(size_t)NN * D_HID];
__device__ float  g_U  [(size_t)NN * D_OUT];
__device__ float  g_RE1[(size_t)NN * D_IN];
__device__ float  g_RE2[(size_t)NN * D_IN];
__device__ double g_sum[D_HID];
__device__ double g_sq [D_HID];
__device__ float  g_mean[D_HID];
__device__ float  g_rstd[D_HID];
__device__ double g_acc[8]; // [0]=sum1 [1]=cnt1 [2]=sum2 [3]=cnt2 [4]=cl_sum

// dtype-detection flags + counters
__device__ int g_mask_mode;   // 0 = uint8, 1 = int32, 2 = float32
__device__ int g_ei_i64;      // 0 = int32, 1 = int64
__device__ int g_cnt[8];

// ---------------- dtype detection ----------------
__global__ void k_zero_cnt() { if (threadIdx.x < 8) g_cnt[threadIdx.x] = 0; }

__global__ void k_detect(const unsigned char* __restrict__ mbytes,
                         const int* __restrict__ eints) {
    int i  = blockIdx.x * blockDim.x + threadIdx.x;
    int st = gridDim.x * blockDim.x;
    int c1 = 0, c3 = 0, ez = 0;
    for (int j = i; j < NN; j += st) {
        unsigned char v = mbytes[j];
        if (v && (j & 3) == 1) c1++;
        if (v && (j & 3) == 3) c3++;
    }
    for (int j = i; j < 100000; j += st)
        if ((j & 1) && eints[j] == 0) ez++;
    atomicAdd(&g_cnt[0], c1);
    atomicAdd(&g_cnt[1], c3);
    atomicAdd(&g_cnt[2], ez);
}

__global__ void k_detect_fin() {
    if (threadIdx.x == 0) {
        if      (g_cnt[1] > 1000) g_mask_mode = 2;
        else if (g_cnt[0] > 1000) g_mask_mode = 0;
        else                      g_mask_mode = 1;
        g_ei_i64 = (g_cnt[2] > 25000) ? 1 : 0;
    }
}

__device__ __forceinline__ bool mask_at(const void* __restrict__ m, int n) {
    int mode = g_mask_mode;
    if (mode == 0) return ((const unsigned char*)m)[n] != 0;
    if (mode == 1) return ((const int*)m)[n] != 0;
    return ((const float*)m)[n] != 0.f;
}

__device__ __forceinline__ int ei_at(const void* __restrict__ ei, long idx) {
    return g_ei_i64 ? (int)((const long long*)ei)[idx] : ((const int*)ei)[idx];
}

// ---------------- tiny utility kernels ----------------
__global__ void k_zero_acc() {
    if (threadIdx.x < 8 && blockIdx.x == 0) g_acc[threadIdx.x] = 0.0;
    int c = blockIdx.x * blockDim.x + threadIdx.x;
    if (c < D_HID) { g_sum[c] = 0.0; g_sq[c] = 0.0; }
}

// mask + dual write: out[i] = H[i] = mask[node] ? 0 : in[i]
__global__ void k_mask_dual(const float* __restrict__ in, const void* __restrict__ m,
                            float* __restrict__ out, float* __restrict__ h,
                            int dshift, long total) {
    long i  = blockIdx.x * (long)blockDim.x + threadIdx.x;
    long st = (long)gridDim.x * blockDim.x;
    for (; i < total; i += st) {
        int node = (int)(i >> dshift);
        float v  = mask_at(m, node) ? 0.f : in[i];
        out[i] = v;
        h[i]   = v;
    }
}

// ---------------- edge scatter: h[dst] += xn[src], one warp per edge ----------------
__device__ __forceinline__ void red_add_v4(float* p, float4 v) {
    asm volatile("red.global.add.v4.f32 [%0], {%1, %2, %3, %4};"
                 :: "l"(p), "f"(v.x), "f"(v.y), "f"(v.z), "f"(v.w) : "memory");
}

__global__ void k_scatter(const float* __restrict__ xn, float* __restrict__ h,
                          const void* __restrict__ ei, int D) {
    int gtid = blockIdx.x * blockDim.x + threadIdx.x;
    int warp = gtid >> 5, lane = gtid & 31;
    int nw   = (gridDim.x * blockDim.x) >> 5;
    int D4   = D >> 2;
    for (int e = warp; e < NE; e += nw) {
        int s = ei_at(ei, e);
        int d = ei_at(ei, (long)NE + e);
        const float4* sp = (const float4*)(xn + (size_t)s * D);
        float*        dp = h + (size_t)d * D;
        for (int c = lane; c < D4; c += 32) {
            float4 v = __ldg(&sp[c]);
            red_add_v4(dp + c * 4, v);
        }
    }
}

// ---------------- TF32 tensor-core GEMM with fused BN ----------------
__device__ __forceinline__ uint32_t f2tf32(float f) {
    uint32_t r;
    asm("cvt.rna.tf32.f32 %0, %1;" : "=r"(r) : "f"(f));
    return r;
}

__device__ __forceinline__ void mma_tf32(float* d, const uint32_t* a, const uint32_t* b) {
    asm volatile(
        "mma.sync.aligned.m16n8k8.row.col.f32.tf32.tf32.f32 "
        "{%0,%1,%2,%3}, {%4,%5,%6,%7}, {%8,%9}, {%0,%1,%2,%3};"
        : "+f"(d[0]), "+f"(d[1]), "+f"(d[2]), "+f"(d[3])
        : "r"(a[0]), "r"(a[1]), "r"(a[2]), "r"(a[3]), "r"(b[0]), "r"(b[1]));
}

// C = act(A) @ B; act = identity (BNA=0) or relu(bn(.)) (BNA=1, channel = A col).
// Epilogue: per-column sum/sumsq of valid C rows -> g_sum/g_sq, via shuffle +
// conflict-free smem slots (NO smem atomics), 1 double atomicAdd per col per CTA.
template <bool BNA>
__global__ void __launch_bounds__(256)
k_gemm(const float* __restrict__ A, const float* __restrict__ B,
       float* __restrict__ C,
       const float* __restrict__ gg, const float* __restrict__ bb,
       int M, int K, int N) {
    __shared__ uint32_t As[128][20];
    __shared__ uint32_t Bs[16][136];
    __shared__ float s_ps[4][128];   // [wm][col] partial sums
    __shared__ float s_pq[4][128];   // [wm][col] partial sumsq

    const int tid  = threadIdx.x;
    const int lane = tid & 31;
    const int warp = tid >> 5;
    const int wm   = warp & 3;
    const int wn   = warp >> 2;
    const int gid  = lane >> 2;
    const int tq   = lane & 3;
    const int brow = blockIdx.y * 128;
    const int bcol = blockIdx.x * 128;

    float acc[2][8][4];
    #pragma unroll
    for (int i = 0; i < 2; i++)
        #pragma unroll
        for (int j = 0; j < 8; j++)
            #pragma unroll
            for (int q = 0; q < 4; q++) acc[i][j][q] = 0.f;

    for (int k0 = 0; k0 < K; k0 += 16) {
        #pragma unroll
        for (int i = 0; i < 2; i++) {
            int idx = tid + i * 256;
            int row = idx >> 2;
            int c4  = (idx & 3) << 2;
            float4 v = make_float4(0.f, 0.f, 0.f, 0.f);
            if (brow + row < M) {
                v = *(const float4*)(A + (size_t)(brow + row) * K + k0 + c4);
                if (BNA) {
                    int ch = k0 + c4;
                    v.x = fmaxf((v.x - g_mean[ch + 0]) * g_rstd[ch + 0] * __ldg(&gg[ch + 0]) + __ldg(&bb[ch + 0]), 0.f);
                    v.y = fmaxf((v.y - g_mean[ch + 1]) * g_rstd[ch + 1] * __ldg(&gg[ch + 1]) + __ldg(&bb[ch + 1]), 0.f);
                    v.z = fmaxf((v.z - g_mean[ch + 2]) * g_rstd[ch + 2] * __ldg(&gg[ch + 2]) + __ldg(&bb[ch + 2]), 0.f);
                    v.w = fmaxf((v.w - g_mean[ch + 3]) * g_rstd[ch + 3] * __ldg(&gg[ch + 3]) + __ldg(&bb[ch + 3]), 0.f);
                }
            }
            As[row][c4 + 0] = f2tf32(v.x);
            As[row][c4 + 1] = f2tf32(v.y);
            As[row][c4 + 2] = f2tf32(v.z);
            As[row][c4 + 3] = f2tf32(v.w);
        }
        #pragma unroll
        for (int i = 0; i < 2; i++) {
            int idx = tid + i * 256;
            int kr = idx >> 5;
            int nc = (idx & 31) << 2;
            float4 v = *(const float4*)(B + (size_t)(k0 + kr) * N + bcol + nc);
            Bs[kr][nc + 0] = f2tf32(v.x);
            Bs[kr][nc + 1] = f2tf32(v.y);
            Bs[kr][nc + 2] = f2tf32(v.z);
            Bs[kr][nc + 3] = f2tf32(v.w);
        }
        __syncthreads();

        #pragma unroll
        for (int kk = 0; kk < 16; kk += 8) {
            uint32_t a[2][4], b[8][2];
            #pragma unroll
            for (int mt = 0; mt < 2; mt++) {
                int r = wm * 32 + mt * 16 + gid;
                a[mt][0] = As[r][kk + tq];
                a[mt][1] = As[r + 8][kk + tq];
                a[mt][2] = As[r][kk + tq + 4];
                a[mt][3] = As[r + 8][kk + tq + 4];
            }
            #pragma unroll
            for (int nt = 0; nt < 8; nt++) {
                int cn = wn * 64 + nt * 8 + gid;
                b[nt][0] = Bs[kk + tq][cn];
                b[nt][1] = Bs[kk + tq + 4][cn];
            }
            #pragma unroll
            for (int mt = 0; mt < 2; mt++)
                #pragma unroll
                for (int nt = 0; nt < 8; nt++)
                    mma_tf32(acc[mt][nt], a[mt], b[nt]);
        }
        __syncthreads();
    }

    // ---- store C ----
    #pragma unroll
    for (int mt = 0; mt < 2; mt++) {
        int r0 = brow + wm * 32 + mt * 16 + gid;
        int r1 = r0 + 8;
        #pragma unroll
        for (int nt = 0; nt < 8; nt++) {
            int c = bcol + wn * 64 + nt * 8 + tq * 2;
            if (r0 < M)
                *(float2*)(C + (size_t)r0 * N + c) = make_float2(acc[mt][nt][0], acc[mt][nt][1]);
            if (r1 < M)
                *(float2*)(C + (size_t)r1 * N + c) = make_float2(acc[mt][nt][2], acc[mt][nt][3]);
        }
    }

    // ---- column stats: register partials -> shfl over gid -> smem slots ----
    float csum[16], csq[16];
    #pragma unroll
    for (int nt = 0; nt < 8; nt++) {
        float s0 = 0.f, s1 = 0.f, q0 = 0.f, q1 = 0.f;
        #pragma unroll
        for (int mt = 0; mt < 2; mt++) {
            int r0 = brow + wm * 32 + mt * 16 + gid;
            int r1 = r0 + 8;
            if (r0 < M) {
                float a = acc[mt][nt][0], b = acc[mt][nt][1];
                s0 += a; q0 += a * a; s1 += b; q1 += b * b;
            }
            if (r1 < M) {
                float a = acc[mt][nt][2], b = acc[mt][nt][3];
                s0 += a; q0 += a * a; s1 += b; q1 += b * b;
            }
        }
        csum[nt * 2] = s0; csum[nt * 2 + 1] = s1;
        csq [nt * 2] = q0; csq [nt * 2 + 1] = q1;
    }
    #pragma unroll
    for (int o = 4; o <= 16; o <<= 1) {
        #pragma unroll
        for (int p = 0; p < 16; p++) {
            csum[p] += __shfl_xor_sync(0xffffffffu, csum[p], o);
            csq[p]  += __shfl_xor_sync(0xffffffffu, csq[p],  o);
        }
    }
    if (gid == 0) {
        #pragma unroll
        for (int nt = 0; nt < 8; nt++) {
            int lc = wn * 64 + nt * 8 + tq * 2;
            s_ps[wm][lc]     = csum[nt * 2];
            s_ps[wm][lc + 1] = csum[nt * 2 + 1];
            s_pq[wm][lc]     = csq[nt * 2];
            s_pq[wm][lc + 1] = csq[nt * 2 + 1];
        }
    }
    __syncthreads();
    if (tid < 128) {
        float ts = s_ps[0][tid] + s_ps[1][tid] + s_ps[2][tid] + s_ps[3][tid];
        float tg = s_pq[0][tid] + s_pq[1][tid] + s_pq[2][tid] + s_pq[3][tid];
        atomicAdd(&g_sum[bcol + tid], (double)ts);
        atomicAdd(&g_sq[bcol + tid],  (double)tg);
    }
}

// mean/rstd from accumulated stats, then reset accumulators for the next GEMM
__global__ void k_bn_fin(int C) {
    int c = threadIdx.x;
    if (c < C) {
        double mu  = g_sum[c] / NN;
        double var = g_sq[c] / NN - mu * mu;
        if (var < 0.0) var = 0.0;
        g_mean[c] = (float)mu;
        g_rstd[c] = (float)rsqrt(var + 1e-5);
    }
    if (c < D_HID) { g_sum[c] = 0.0; g_sq[c] = 0.0; }
}

// out = relu(bn(in)); optionally also write a second copy (next layer's H)
__global__ void k_bn_apply_dual(const float* __restrict__ in, float* __restrict__ out,
                                float* __restrict__ h,
                                const float* __restrict__ gg, const float* __restrict__ bb,
                                int cmask, long total) {
    long i  = blockIdx.x * (long)blockDim.x + threadIdx.x;
    long st = (long)gridDim.x * blockDim.x;
    for (; i < total; i += st) {
        int c   = (int)(i & cmask);
        float v = (in[i] - g_mean[c]) * g_rstd[c] * __ldg(&gg[c]) + __ldg(&bb[c]);
        v = v > 0.f ? v : 0.f;
        out[i] = v;
        if (h) h[i] = v;
    }
}

// ---------------- cosine losses (D = 128, one warp per node) ----------------
__global__ void k_cos(const float* __restrict__ a, const float* __restrict__ b,
                      const void* __restrict__ m, int useMask, int accOff) {
    int gtid = blockIdx.x * blockDim.x + threadIdx.x;
    int warp = gtid >> 5, lane = gtid & 31;
    int nw   = (gridDim.x * blockDim.x) >> 5;
    double ls = 0.0, lc = 0.0;
    for (int n = warp; n < NN; n += nw) {
        if (useMask && !mask_at(m, n)) continue;
        float4 va = *((const float4*)(a + (size_t)n * 128) + lane);
        float4 vb = *((const float4*)(b + (size_t)n * 128) + lane);
        float dot = va.x * vb.x + va.y * vb.y + va.z * vb.z + va.w * vb.w;
        float na  = va.x * va.x + va.y * va.y + va.z * va.z + va.w * va.w;
        float nb  = vb.x * vb.x + vb.y * vb.y + vb.z * vb.z + vb.w * vb.w;
        #pragma unroll
        for (int o = 16; o; o >>= 1) {
            dot += __shfl_xor_sync(0xffffffffu, dot, o);
            na  += __shfl_xor_sync(0xffffffffu, na,  o);
            nb  += __shfl_xor_sync(0xffffffffu, nb,  o);
        }
        if (lane == 0) {
            float cs = dot / (fmaxf(sqrtf(na), 1e-12f) * fmaxf(sqrtf(nb), 1e-12f));
            ls += 1.0 - (double)cs;
            lc += 1.0;
        }
    }
    if (lane == 0) {
        atomicAdd(&g_acc[accOff], ls);
        if (useMask) atomicAdd(&g_acc[accOff + 1], lc);
    }
}

__global__ void k_finalize(float* out) {
    double v = g_acc[0] / g_acc[1] + g_acc[2] / g_acc[3] + 0.1 * (g_acc[4] / (double)NN);
    out[0] = (float)v;
}

// ---------------- host-side orchestration ----------------
static void run_layer(const float* in, int din, const void* ei,
                      const float* w1, const float* w2,
                      const float* bg, const float* bb,
                      const float* ng, const float* nb,
                      int dout, float* outbuf, float* hnext,
                      float* H, float* T, float* U) {
    k_scatter<<<40000, 256>>>(in, H, ei, din);

    dim3 g1(D_HID / 128, (NN + 127) / 128);
    k_gemm<false><<<g1, 256>>>(H, w1, T, nullptr, nullptr, NN, din, D_HID);
    k_bn_fin<<<1, D_HID>>>(D_HID);

    dim3 g2(dout / 128, (NN + 127) / 128);
    k_gemm<true><<<g2, 256>>>(T, w2, U, bg, bb, NN, D_HID, dout);
    k_bn_fin<<<1, D_HID>>>(dout);

    k_bn_apply_dual<<<8192, 256>>>(U, outbuf, hnext, ng, nb, dout - 1, (long)NN * dout);
}

extern "C" void kernel_launch(void* const* d_in, const int* in_sizes, int n_in,
                              void* d_out, int out_size) {
    const float* x   = (const float*)d_in[0];
    const void*  ei1 = d_in[1];
    const void*  ei2 = d_in[2];
    const void*  m1  = d_in[3];
    const void*  m2  = d_in[4];
    // d_in[5] = batch : dead code in the reference
    const float* e0_w1 = (const float*)d_in[6];
    const float* e0_w2 = (const float*)d_in[7];
    const float* e0_bg = (const float*)d_in[8];
    const float* e0_bb = (const float*)d_in[9];
    const float* e0_ng = (const float*)d_in[10];
    const float* e0_nb = (const float*)d_in[11];
    const float* e1_w1 = (const float*)d_in[12];
    const float* e1_w2 = (const float*)d_in[13];
    const float* e1_bg = (const float*)d_in[14];
    const float* e1_bb = (const float*)d_in[15];
    const float* e1_ng = (const float*)d_in[16];
    const float* e1_nb = (const float*)d_in[17];
    const float* d_w1  = (const float*)d_in[18];
    const float* d_w2  = (const float*)d_in[19];
    const float* d_bg  = (const float*)d_in[20];
    const float* d_bb  = (const float*)d_in[21];
    const float* d_ng  = (const float*)d_in[22];
    const float* d_nb  = (const float*)d_in[23];
    float* out = (float*)d_out;

    float *X1, *XN, *H, *T, *U, *RE1, *RE2;
    cudaGetSymbolAddress((void**)&X1,  g_X1);
    cudaGetSymbolAddress((void**)&XN,  g_XN);
    cudaGetSymbolAddress((void**)&H,   g_H);
    cudaGetSymbolAddress((void**)&T,   g_T);
    cudaGetSymbolAddress((void**)&U,   g_U);
    cudaGetSymbolAddress((void**)&RE1, g_RE1);
    cudaGetSymbolAddress((void**)&RE2, g_RE2);

    // dtype auto-detection
    k_zero_cnt<<<1, 32>>>();
    k_detect<<<128, 256>>>((const unsigned char*)m1, (const int*)ei1);
    k_detect_fin<<<1, 32>>>();

    k_zero_acc<<<2, 256>>>();

    for (int pass = 0; pass < 2; pass++) {
        const void* ei = pass == 0 ? ei1 : ei2;
        const void* m  = pass == 0 ? m1  : m2;
        float*      RE = pass == 0 ? RE1 : RE2;

        // x1 = where(mask,0,x); also preload scatter base H
        k_mask_dual<<<8192, 256>>>(x, m, X1, H, 7, (long)NN * D_IN);

        // encoder layer 0: 128 -> 256 (also preloads next H)
        run_layer(X1, D_IN, ei, e0_w1, e0_w2, e0_bg, e0_bb, e0_ng, e0_nb,
                  D_OUT, XN, H, H, T, U);
        // encoder layer 1: 256 -> 256
        run_layer(XN, D_OUT, ei, e1_w1, e1_w2, e1_bg, e1_bb, e1_ng, e1_nb,
                  D_OUT, XN, nullptr, H, T, U);

        // re_h = where(mask,0,h); preload decoder scatter base H
        k_mask_dual<<<8192, 256>>>(XN, m, XN, H, 8, (long)NN * D_OUT);

        // decoder layer: 256 -> 128
        run_layer(XN, D_OUT, ei, d_w1, d_w2, d_bg, d_bb, d_ng, d_nb,
                  D_IN, RE, nullptr, H, T, U);

        // masked reconstruction loss
        k_cos<<<512, 256>>>(RE, x, m, 1, pass * 2);
    }

    // contrastive term over all nodes
    k_cos<<<512, 256>>>(RE2, RE1, nullptr, 0, 4);
    k_finalize<<<1, 1>>>(out);
    (void)in_sizes; (void)n_in; (void)out_size;
}

// round 6
// speedup vs baseline: 2.6227x; 1.0132x over previous
#include <cuda_runtime.h>
#include <math.h>
#include <stdint.h>

#define NN    50000
#define NE    320000
#define D_IN  128
#define D_OUT 256
#define D_HID 512

// ---------------- scratch (static device globals; no allocation) ----------------
__device__ float  g_X1 [(size_t)NN * D_IN];
__device__ float  g_XN [(size_t)NN * D_OUT];
__device__ float  g_H  [(size_t)NN * D_OUT];
__device__ float  g_T  [(size_t)NN * D_HID];
__device__ float  g_U  [(size_t)NN * D_OUT];
__device__ float  g_RE1[(size_t)NN * D_IN];
__device__ float  g_RE2[(size_t)NN * D_IN];
__device__ double g_sum[D_HID];
__device__ double g_sq [D_HID];
__device__ float  g_mean[D_HID];
__device__ float  g_rstd[D_HID];
__device__ double g_acc[8]; // [0]=sum1 [1]=cnt1 [2]=sum2 [3]=cnt2 [4]=cl_sum

// CSR scratch (rebuilt per pass, reused across the pass's 3 layers)
__device__ int g_deg   [NN];
__device__ int g_rowptr[NN + 1];
__device__ int g_cursor[NN];
__device__ int g_col   [NE];

// dtype-detection flags + counters
__device__ int g_mask_mode;   // 0 = uint8, 1 = int32, 2 = float32
__device__ int g_ei_i64;      // 0 = int32, 1 = int64
__device__ int g_cnt[8];

// ---------------- dtype detection ----------------
__global__ void k_zero_cnt() { if (threadIdx.x < 8) g_cnt[threadIdx.x] = 0; }

__global__ void k_detect(const unsigned char* __restrict__ mbytes,
                         const int* __restrict__ eints) {
    int i  = blockIdx.x * blockDim.x + threadIdx.x;
    int st = gridDim.x * blockDim.x;
    int c1 = 0, c3 = 0, ez = 0;
    for (int j = i; j < NN; j += st) {
        unsigned char v = mbytes[j];
        if (v && (j & 3) == 1) c1++;
        if (v && (j & 3) == 3) c3++;
    }
    for (int j = i; j < 100000; j += st)
        if ((j & 1) && eints[j] == 0) ez++;
    atomicAdd(&g_cnt[0], c1);
    atomicAdd(&g_cnt[1], c3);
    atomicAdd(&g_cnt[2], ez);
}

__global__ void k_detect_fin() {
    if (threadIdx.x == 0) {
        if      (g_cnt[1] > 1000) g_mask_mode = 2;
        else if (g_cnt[0] > 1000) g_mask_mode = 0;
        else                      g_mask_mode = 1;
        g_ei_i64 = (g_cnt[2] > 25000) ? 1 : 0;
    }
}

__device__ __forceinline__ bool mask_at(const void* __restrict__ m, int n) {
    int mode = g_mask_mode;
    if (mode == 0) return ((const unsigned char*)m)[n] != 0;
    if (mode == 1) return ((const int*)m)[n] != 0;
    return ((const float*)m)[n] != 0.f;
}

__device__ __forceinline__ int ei_at(const void* __restrict__ ei, long idx) {
    return g_ei_i64 ? (int)((const long long*)ei)[idx] : ((const int*)ei)[idx];
}

// ---------------- tiny utility kernels ----------------
__global__ void k_zero_acc() {
    if (threadIdx.x < 8 && blockIdx.x == 0) g_acc[threadIdx.x] = 0.0;
    int c = blockIdx.x * blockDim.x + threadIdx.x;
    if (c < D_HID) { g_sum[c] = 0.0; g_sq[c] = 0.0; }
}

// out[i] = mask[node] ? 0 : in[i]   (works in-place)
__global__ void k_mask(const float* __restrict__ in, const void* __restrict__ m,
                       float* __restrict__ out, int dshift, long total) {
    long i  = blockIdx.x * (long)blockDim.x + threadIdx.x;
    long st = (long)gridDim.x * blockDim.x;
    for (; i < total; i += st) {
        int node = (int)(i >> dshift);
        out[i] = mask_at(m, node) ? 0.f : in[i];
    }
}

// ---------------- CSR build (per pass) ----------------
__global__ void k_zero_deg() {
    int i  = blockIdx.x * blockDim.x + threadIdx.x;
    int st = gridDim.x * blockDim.x;
    for (; i < NN; i += st) g_deg[i] = 0;
}

__global__ void k_count(const void* __restrict__ ei) {
    int e  = blockIdx.x * blockDim.x + threadIdx.x;
    int st = gridDim.x * blockDim.x;
    for (; e < NE; e += st)
        atomicAdd(&g_deg[ei_at(ei, (long)NE + e)], 1);
}

// single-block exclusive scan over g_deg -> g_rowptr, g_cursor
__global__ void __launch_bounds__(1024) k_scan() {
    __shared__ int ssum[1024];
    const int t = threadIdx.x;
    const int C = (NN + 1023) / 1024;           // 49
    int lo = t * C, hi = min(NN, lo + C);
    int s = 0;
    for (int i = lo; i < hi; i++) s += g_deg[i];
    ssum[t] = s;
    __syncthreads();
    #pragma unroll
    for (int o = 1; o < 1024; o <<= 1) {
        int v = (t >= o) ? ssum[t - o] : 0;
        __syncthreads();
        ssum[t] += v;
        __syncthreads();
    }
    int run = (t == 0) ? 0 : ssum[t - 1];
    for (int i = lo; i < hi; i++) {
        int d = g_deg[i];
        g_rowptr[i] = run;
        g_cursor[i] = run;
        run += d;
    }
    if (t == 1023) g_rowptr[NN] = run;
}

__global__ void k_fill(const void* __restrict__ ei) {
    int e  = blockIdx.x * blockDim.x + threadIdx.x;
    int st = gridDim.x * blockDim.x;
    for (; e < NE; e += st) {
        int s = ei_at(ei, e);
        int d = ei_at(ei, (long)NE + e);
        int slot = atomicAdd(&g_cursor[d], 1);
        g_col[slot] = s;
    }
}

// ---------------- CSR aggregate: h[n] = in[n] + sum_{s in adj(n)} in[s] ----------------
// One warp per node, register accumulators, no atomics.
template <int D>
__global__ void k_aggregate(const float* __restrict__ in, float* __restrict__ h) {
    const int gtid = blockIdx.x * blockDim.x + threadIdx.x;
    const int warp = gtid >> 5;
    const int lane = gtid & 31;
    if (warp >= NN) return;
    const int D4 = D / 4;
    const float4* ip = (const float4*)in;

    float4 a0 = ip[(size_t)warp * D4 + lane];
    float4 a1 = (D == 256) ? ip[(size_t)warp * D4 + 32 + lane]
                           : make_float4(0.f, 0.f, 0.f, 0.f);

    int j   = g_rowptr[warp];
    int end = g_rowptr[warp + 1];
    // 2-way unrolled neighbor loop for MLP
    for (; j + 1 < end; j += 2) {
        int s0 = __ldg(&g_col[j]);
        int s1 = __ldg(&g_col[j + 1]);
        float4 v0 = __ldg(&ip[(size_t)s0 * D4 + lane]);
        float4 w0 = __ldg(&ip[(size_t)s1 * D4 + lane]);
        a0.x += v0.x + w0.x; a0.y += v0.y + w0.y;
        a0.z += v0.z + w0.z; a0.w += v0.w + w0.w;
        if (D == 256) {
            float4 v1 = __ldg(&ip[(size_t)s0 * D4 + 32 + lane]);
            float4 w1 = __ldg(&ip[(size_t)s1 * D4 + 32 + lane]);
            a1.x += v1.x + w1.x; a1.y += v1.y + w1.y;
            a1.z += v1.z + w1.z; a1.w += v1.w + w1.w;
        }
    }
    if (j < end) {
        int s0 = __ldg(&g_col[j]);
        float4 v0 = __ldg(&ip[(size_t)s0 * D4 + lane]);
        a0.x += v0.x; a0.y += v0.y; a0.z += v0.z; a0.w += v0.w;
        if (D == 256) {
            float4 v1 = __ldg(&ip[(size_t)s0 * D4 + 32 + lane]);
            a1.x += v1.x; a1.y += v1.y; a1.z += v1.z; a1.w += v1.w;
        }
    }
    float4* hp = (float4*)h;
    hp[(size_t)warp * D4 + lane] = a0;
    if (D == 256) hp[(size_t)warp * D4 + 32 + lane] = a1;
}

// ---------------- TF32 tensor-core GEMM with fused BN ----------------
__device__ __forceinline__ uint32_t f2tf32(float f) {
    uint32_t r;
    asm("cvt.rna.tf32.f32 %0, %1;" : "=r"(r) : "f"(f));
    return r;
}

__device__ __forceinline__ void mma_tf32(float* d, const uint32_t* a, const uint32_t* b) {
    asm volatile(
        "mma.sync.aligned.m16n8k8.row.col.f32.tf32.tf32.f32 "
        "{%0,%1,%2,%3}, {%4,%5,%6,%7}, {%8,%9}, {%0,%1,%2,%3};"
        : "+f"(d[0]), "+f"(d[1]), "+f"(d[2]), "+f"(d[3])
        : "r"(a[0]), "r"(a[1]), "r"(a[2]), "r"(a[3]), "r"(b[0]), "r"(b[1]));
}

// C = act(A) @ B; act = identity (BNA=0) or relu(bn(.)) (BNA=1, channel = A col).
// Epilogue: per-column sum/sumsq via shfl + conflict-free smem, 1 double atomic/col/CTA.
template <bool BNA>
__global__ void __launch_bounds__(256)
k_gemm(const float* __restrict__ A, const float* __restrict__ B,
       float* __restrict__ C,
       const float* __restrict__ gg, const float* __restrict__ bb,
       int M, int K, int N) {
    __shared__ uint32_t As[128][20];
    __shared__ uint32_t Bs[16][136];
    __shared__ float s_ps[4][128];
    __shared__ float s_pq[4][128];

    const int tid  = threadIdx.x;
    const int lane = tid & 31;
    const int warp = tid >> 5;
    const int wm   = warp & 3;
    const int wn   = warp >> 2;
    const int gid  = lane >> 2;
    const int tq   = lane & 3;
    const int brow = blockIdx.y * 128;
    const int bcol = blockIdx.x * 128;

    float acc[2][8][4];
    #pragma unroll
    for (int i = 0; i < 2; i++)
        #pragma unroll
        for (int j = 0; j < 8; j++)
            #pragma unroll
            for (int q = 0; q < 4; q++) acc[i][j][q] = 0.f;

    for (int k0 = 0; k0 < K; k0 += 16) {
        #pragma unroll
        for (int i = 0; i < 2; i++) {
            int idx = tid + i * 256;
            int row = idx >> 2;
            int c4  = (idx & 3) << 2;
            float4 v = make_float4(0.f, 0.f, 0.f, 0.f);
            if (brow + row < M) {
                v = *(const float4*)(A + (size_t)(brow + row) * K + k0 + c4);
                if (BNA) {
                    int ch = k0 + c4;
                    v.x = fmaxf((v.x - g_mean[ch + 0]) * g_rstd[ch + 0] * __ldg(&gg[ch + 0]) + __ldg(&bb[ch + 0]), 0.f);
                    v.y = fmaxf((v.y - g_mean[ch + 1]) * g_rstd[ch + 1] * __ldg(&gg[ch + 1]) + __ldg(&bb[ch + 1]), 0.f);
                    v.z = fmaxf((v.z - g_mean[ch + 2]) * g_rstd[ch + 2] * __ldg(&gg[ch + 2]) + __ldg(&bb[ch + 2]), 0.f);
                    v.w = fmaxf((v.w - g_mean[ch + 3]) * g_rstd[ch + 3] * __ldg(&gg[ch + 3]) + __ldg(&bb[ch + 3]), 0.f);
                }
            }
            As[row][c4 + 0] = f2tf32(v.x);
            As[row][c4 + 1] = f2tf32(v.y);
            As[row][c4 + 2] = f2tf32(v.z);
            As[row][c4 + 3] = f2tf32(v.w);
        }
        #pragma unroll
        for (int i = 0; i < 2; i++) {
            int idx = tid + i * 256;
            int kr = idx >> 5;
            int nc = (idx & 31) << 2;
            float4 v = *(const float4*)(B + (size_t)(k0 + kr) * N + bcol + nc);
            Bs[kr][nc + 0] = f2tf32(v.x);
            Bs[kr][nc + 1] = f2tf32(v.y);
            Bs[kr][nc + 2] = f2tf32(v.z);
            Bs[kr][nc + 3] = f2tf32(v.w);
        }
        __syncthreads();

        #pragma unroll
        for (int kk = 0; kk < 16; kk += 8) {
            uint32_t a[2][4], b[8][2];
            #pragma unroll
            for (int mt = 0; mt < 2; mt++) {
                int r = wm * 32 + mt * 16 + gid;
                a[mt][0] = As[r][kk + tq];
                a[mt][1] = As[r + 8][kk + tq];
                a[mt][2] = As[r][kk + tq + 4];
                a[mt][3] = As[r + 8][kk + tq + 4];
            }
            #pragma unroll
            for (int nt = 0; nt < 8; nt++) {
                int cn = wn * 64 + nt * 8 + gid;
                b[nt][0] = Bs[kk + tq][cn];
                b[nt][1] = Bs[kk + tq + 4][cn];
            }
            #pragma unroll
            for (int mt = 0; mt < 2; mt++)
                #pragma unroll
                for (int nt = 0; nt < 8; nt++)
                    mma_tf32(acc[mt][nt], a[mt], b[nt]);
        }
        __syncthreads();
    }

    // ---- store C ----
    #pragma unroll
    for (int mt = 0; mt < 2; mt++) {
        int r0 = brow + wm * 32 + mt * 16 + gid;
        int r1 = r0 + 8;
        #pragma unroll
        for (int nt = 0; nt < 8; nt++) {
            int c = bcol + wn * 64 + nt * 8 + tq * 2;
            if (r0 < M)
                *(float2*)(C + (size_t)r0 * N + c) = make_float2(acc[mt][nt][0], acc[mt][nt][1]);
            if (r1 < M)
                *(float2*)(C + (size_t)r1 * N + c) = make_float2(acc[mt][nt][2], acc[mt][nt][3]);
        }
    }

    // ---- column stats ----
    float csum[16], csq[16];
    #pragma unroll
    for (int nt = 0; nt < 8; nt++) {
        float s0 = 0.f, s1 = 0.f, q0 = 0.f, q1 = 0.f;
        #pragma unroll
        for (int mt = 0; mt < 2; mt++) {
            int r0 = brow + wm * 32 + mt * 16 + gid;
            int r1 = r0 + 8;
            if (r0 < M) {
                float a = acc[mt][nt][0], b = acc[mt][nt][1];
                s0 += a; q0 += a * a; s1 += b; q1 += b * b;
            }
            if (r1 < M) {
                float a = acc[mt][nt][2], b = acc[mt][nt][3];
                s0 += a; q0 += a * a; s1 += b; q1 += b * b;
            }
        }
        csum[nt * 2] = s0; csum[nt * 2 + 1] = s1;
        csq [nt * 2] = q0; csq [nt * 2 + 1] = q1;
    }
    #pragma unroll
    for (int o = 4; o <= 16; o <<= 1) {
        #pragma unroll
        for (int p = 0; p < 16; p++) {
            csum[p] += __shfl_xor_sync(0xffffffffu, csum[p], o);
            csq[p]  += __shfl_xor_sync(0xffffffffu, csq[p],  o);
        }
    }
    if (gid == 0) {
        #pragma unroll
        for (int nt = 0; nt < 8; nt++) {
            int lc = wn * 64 + nt * 8 + tq * 2;
            s_ps[wm][lc]     = csum[nt * 2];
            s_ps[wm][lc + 1] = csum[nt * 2 + 1];
            s_pq[wm][lc]     = csq[nt * 2];
            s_pq[wm][lc + 1] = csq[nt * 2 + 1];
        }
    }
    __syncthreads();
    if (tid < 128) {
        float ts = s_ps[0][tid] + s_ps[1][tid] + s_ps[2][tid] + s_ps[3][tid];
        float tg = s_pq[0][tid] + s_pq[1][tid] + s_pq[2][tid] + s_pq[3][tid];
        atomicAdd(&g_sum[bcol + tid], (double)ts);
        atomicAdd(&g_sq[bcol + tid],  (double)tg);
    }
}

__global__ void k_bn_fin(int C) {
    int c = threadIdx.x;
    if (c < C) {
        double mu  = g_sum[c] / NN;
        double var = g_sq[c] / NN - mu * mu;
        if (var < 0.0) var = 0.0;
        g_mean[c] = (float)mu;
        g_rstd[c] = (float)rsqrt(var + 1e-5);
    }
    if (c < D_HID) { g_sum[c] = 0.0; g_sq[c] = 0.0; }
}

__global__ void k_bn_apply(const float* __restrict__ in, float* __restrict__ out,
                           const float* __restrict__ gg, const float* __restrict__ bb,
                           int cmask, long total) {
    long i  = blockIdx.x * (long)blockDim.x + threadIdx.x;
    long st = (long)gridDim.x * blockDim.x;
    for (; i < total; i += st) {
        int c   = (int)(i & cmask);
        float v = (in[i] - g_mean[c]) * g_rstd[c] * __ldg(&gg[c]) + __ldg(&bb[c]);
        out[i] = v > 0.f ? v : 0.f;
    }
}

// ---------------- cosine losses (D = 128, one warp per node) ----------------
__global__ void k_cos(const float* __restrict__ a, const float* __restrict__ b,
                      const void* __restrict__ m, int useMask, int accOff) {
    int gtid = blockIdx.x * blockDim.x + threadIdx.x;
    int warp = gtid >> 5, lane = gtid & 31;
    int nw   = (gridDim.x * blockDim.x) >> 5;
    double ls = 0.0, lc = 0.0;
    for (int n = warp; n < NN; n += nw) {
        if (useMask && !mask_at(m, n)) continue;
        float4 va = *((const float4*)(a + (size_t)n * 128) + lane);
        float4 vb = *((const float4*)(b + (size_t)n * 128) + lane);
        float dot = va.x * vb.x + va.y * vb.y + va.z * vb.z + va.w * vb.w;
        float na  = va.x * va.x + va.y * va.y + va.z * va.z + va.w * va.w;
        float nb  = vb.x * vb.x + vb.y * vb.y + vb.z * vb.z + vb.w * vb.w;
        #pragma unroll
        for (int o = 16; o; o >>= 1) {
            dot += __shfl_xor_sync(0xffffffffu, dot, o);
            na  += __shfl_xor_sync(0xffffffffu, na,  o);
            nb  += __shfl_xor_sync(0xffffffffu, nb,  o);
        }
        if (lane == 0) {
            float cs = dot / (fmaxf(sqrtf(na), 1e-12f) * fmaxf(sqrtf(nb), 1e-12f));
            ls += 1.0 - (double)cs;
            lc += 1.0;
        }
    }
    if (lane == 0) {
        atomicAdd(&g_acc[accOff], ls);
        if (useMask) atomicAdd(&g_acc[accOff + 1], lc);
    }
}

__global__ void k_finalize(float* out) {
    double v = g_acc[0] / g_acc[1] + g_acc[2] / g_acc[3] + 0.1 * (g_acc[4] / (double)NN);
    out[0] = (float)v;
}

// ---------------- host-side orchestration ----------------
static void run_layer(const float* in, int din,
                      const float* w1, const float* w2,
                      const float* bg, const float* bb,
                      const float* ng, const float* nb,
                      int dout, float* outbuf,
                      float* H, float* T, float* U) {
    int nblk = (NN * 32 + 255) / 256;   // one warp per node
    if (din == 128) k_aggregate<128><<<nblk, 256>>>(in, H);
    else            k_aggregate<256><<<nblk, 256>>>(in, H);

    dim3 g1(D_HID / 128, (NN + 127) / 128);
    k_gemm<false><<<g1, 256>>>(H, w1, T, nullptr, nullptr, NN, din, D_HID);
    k_bn_fin<<<1, D_HID>>>(D_HID);

    dim3 g2(dout / 128, (NN + 127) / 128);
    k_gemm<true><<<g2, 256>>>(T, w2, U, bg, bb, NN, D_HID, dout);
    k_bn_fin<<<1, D_HID>>>(dout);

    k_bn_apply<<<8192, 256>>>(U, outbuf, ng, nb, dout - 1, (long)NN * dout);
}

extern "C" void kernel_launch(void* const* d_in, const int* in_sizes, int n_in,
                              void* d_out, int out_size) {
    const float* x   = (const float*)d_in[0];
    const void*  ei1 = d_in[1];
    const void*  ei2 = d_in[2];
    const void*  m1  = d_in[3];
    const void*  m2  = d_in[4];
    // d_in[5] = batch : dead code in the reference
    const float* e0_w1 = (const float*)d_in[6];
    const float* e0_w2 = (const float*)d_in[7];
    const float* e0_bg = (const float*)d_in[8];
    const float* e0_bb = (const float*)d_in[9];
    const float* e0_ng = (const float*)d_in[10];
    const float* e0_nb = (const float*)d_in[11];
    const float* e1_w1 = (const float*)d_in[12];
    const float* e1_w2 = (const float*)d_in[13];
    const float* e1_bg = (const float*)d_in[14];
    const float* e1_bb = (const float*)d_in[15];
    const float* e1_ng = (const float*)d_in[16];
    const float* e1_nb = (const float*)d_in[17];
    const float* d_w1  = (const float*)d_in[18];
    const float* d_w2  = (const float*)d_in[19];
    const float* d_bg  = (const float*)d_in[20];
    const float* d_bb  = (const float*)d_in[21];
    const float* d_ng  = (const float*)d_in[22];
    const float* d_nb  = (const float*)d_in[23];
    float* out = (float*)d_out;

    float *X1, *XN, *H, *T, *U, *RE1, *RE2;
    cudaGetSymbolAddress((void**)&X1,  g_X1);
    cudaGetSymbolAddress((void**)&XN,  g_XN);
    cudaGetSymbolAddress((void**)&H,   g_H);
    cudaGetSymbolAddress((void**)&T,   g_T);
    cudaGetSymbolAddress((void**)&U,   g_U);
    cudaGetSymbolAddress((void**)&RE1, g_RE1);
    cudaGetSymbolAddress((void**)&RE2, g_RE2);

    // dtype auto-detection
    k_zero_cnt<<<1, 32>>>();
    k_detect<<<128, 256>>>((const unsigned char*)m1, (const int*)ei1);
    k_detect_fin<<<1, 32>>>();

    k_zero_acc<<<2, 256>>>();

    for (int pass = 0; pass < 2; pass++) {
        const void* ei = pass == 0 ? ei1 : ei2;
        const void* m  = pass == 0 ? m1  : m2;
        float*      RE = pass == 0 ? RE1 : RE2;

        // build CSR for this pass (reused by all 3 layers)
        k_zero_deg<<<256, 256>>>();
        k_count<<<1024, 256>>>(ei);
        k_scan<<<1, 1024>>>();
        k_fill<<<1024, 256>>>(ei);

        // x1 = where(mask,0,x)
        k_mask<<<8192, 256>>>(x, m, X1, 7, (long)NN * D_IN);

        // encoder layer 0: 128 -> 256
        run_layer(X1, D_IN, e0_w1, e0_w2, e0_bg, e0_bb, e0_ng, e0_nb,
                  D_OUT, XN, H, T, U);
        // encoder layer 1: 256 -> 256
        run_layer(XN, D_OUT, e1_w1, e1_w2, e1_bg, e1_bb, e1_ng, e1_nb,
                  D_OUT, XN, H, T, U);

        // re_h = where(mask,0,h)
        k_mask<<<8192, 256>>>(XN, m, XN, 8, (long)NN * D_OUT);

        // decoder layer: 256 -> 128
        run_layer(XN, D_OUT, d_w1, d_w2, d_bg, d_bb, d_ng, d_nb,
                  D_IN, RE, H, T, U);

        // masked reconstruction loss
        k_cos<<<512, 256>>>(RE, x, m, 1, pass * 2);
    }

    // contrastive term over all nodes
    k_cos<<<512, 256>>>(RE2, RE1, nullptr, 0, 4);
    k_finalize<<<1, 1>>>(out);
    (void)in_sizes; (void)n_in; (void)out_size;
}

// round 7
// speedup vs baseline: 2.8596x; 1.0903x over previous
#include <cuda_runtime.h>
#include <math.h>
#include <stdint.h>

#define NN    50000
#define NE    320000
#define D_IN  128
#define D_OUT 256
#define D_HID 512

// ---------------- scratch (static device globals; no allocation) ----------------
__device__ float  g_H  [(size_t)NN * D_OUT];
__device__ float  g_T  [(size_t)NN * D_HID];
__device__ float  g_U  [(size_t)NN * D_OUT];
__device__ float  g_RE1[(size_t)NN * D_IN];
__device__ float  g_RE2[(size_t)NN * D_IN];
__device__ float  g_WT [655360];          // transposed weights arena
__device__ double g_sum[D_HID];
__device__ double g_sq [D_HID];
__device__ float  g_mean[D_HID];
__device__ float  g_rstd[D_HID];
__device__ double g_acc[8]; // [0]=sum1 [1]=cnt1 [2]=sum2 [3]=cnt2 [4]=cl_sum

// CSR scratch (rebuilt per pass)
__device__ int g_deg   [NN];
__device__ int g_rowptr[NN + 1];
__device__ int g_cursor[NN];
__device__ int g_col   [NE];

// dtype-detection flags + counters
__device__ int g_mask_mode;   // 0 = uint8, 1 = int32, 2 = float32
__device__ int g_ei_i64;      // 0 = int32, 1 = int64
__device__ int g_cnt[8];

// ---------------- dtype detection ----------------
__global__ void k_zero_cnt() { if (threadIdx.x < 8) g_cnt[threadIdx.x] = 0; }

__global__ void k_detect(const unsigned char* __restrict__ mbytes,
                         const int* __restrict__ eints) {
    int i  = blockIdx.x * blockDim.x + threadIdx.x;
    int st = gridDim.x * blockDim.x;
    int c1 = 0, c3 = 0, ez = 0;
    for (int j = i; j < NN; j += st) {
        unsigned char v = mbytes[j];
        if (v && (j & 3) == 1) c1++;
        if (v && (j & 3) == 3) c3++;
    }
    for (int j = i; j < 100000; j += st)
        if ((j & 1) && eints[j] == 0) ez++;
    atomicAdd(&g_cnt[0], c1);
    atomicAdd(&g_cnt[1], c3);
    atomicAdd(&g_cnt[2], ez);
}

__global__ void k_detect_fin() {
    if (threadIdx.x == 0) {
        if      (g_cnt[1] > 1000) g_mask_mode = 2;
        else if (g_cnt[0] > 1000) g_mask_mode = 0;
        else                      g_mask_mode = 1;
        g_ei_i64 = (g_cnt[2] > 25000) ? 1 : 0;
    }
}

__device__ __forceinline__ bool mask_at(const void* __restrict__ m, int n) {
    int mode = g_mask_mode;
    if (mode == 0) return ((const unsigned char*)m)[n] != 0;
    if (mode == 1) return ((const int*)m)[n] != 0;
    return ((const float*)m)[n] != 0.f;
}

__device__ __forceinline__ int ei_at(const void* __restrict__ ei, long idx) {
    return g_ei_i64 ? (int)((const long long*)ei)[idx] : ((const int*)ei)[idx];
}

// ---------------- tiny utility kernels ----------------
__global__ void k_zero_acc() {
    if (threadIdx.x < 8 && blockIdx.x == 0) g_acc[threadIdx.x] = 0.0;
    int c = blockIdx.x * blockDim.x + threadIdx.x;
    if (c < D_HID) { g_sum[c] = 0.0; g_sq[c] = 0.0; }
}

// ---------------- weight transpose: W[K][N] -> WT[N][K] ----------------
__global__ void k_transpose(const float* __restrict__ W, float* __restrict__ WT,
                            int K, int N) {
    __shared__ float tile[32][33];
    int n0 = blockIdx.x * 32, k0 = blockIdx.y * 32;
    int tx = threadIdx.x, ty = threadIdx.y;
    #pragma unroll
    for (int i = 0; i < 4; i++)
        tile[ty + i * 8][tx] = W[(size_t)(k0 + ty + i * 8) * N + n0 + tx];
    __syncthreads();
    #pragma unroll
    for (int i = 0; i < 4; i++)
        WT[(size_t)(n0 + ty + i * 8) * K + k0 + tx] = tile[tx][ty + i * 8];
}

// ---------------- CSR build (per pass) ----------------
__global__ void k_zero_deg() {
    int i  = blockIdx.x * blockDim.x + threadIdx.x;
    int st = gridDim.x * blockDim.x;
    for (; i < NN; i += st) g_deg[i] = 0;
}

__global__ void k_count(const void* __restrict__ ei) {
    int e  = blockIdx.x * blockDim.x + threadIdx.x;
    int st = gridDim.x * blockDim.x;
    for (; e < NE; e += st)
        atomicAdd(&g_deg[ei_at(ei, (long)NE + e)], 1);
}

__global__ void __launch_bounds__(1024) k_scan() {
    __shared__ int ssum[1024];
    const int t = threadIdx.x;
    const int C = (NN + 1023) / 1024;
    int lo = t * C, hi = min(NN, lo + C);
    int s = 0;
    for (int i = lo; i < hi; i++) s += g_deg[i];
    ssum[t] = s;
    __syncthreads();
    #pragma unroll
    for (int o = 1; o < 1024; o <<= 1) {
        int v = (t >= o) ? ssum[t - o] : 0;
        __syncthreads();
        ssum[t] += v;
        __syncthreads();
    }
    int run = (t == 0) ? 0 : ssum[t - 1];
    for (int i = lo; i < hi; i++) {
        int d = g_deg[i];
        g_rowptr[i] = run;
        g_cursor[i] = run;
        run += d;
    }
    if (t == 1023) g_rowptr[NN] = run;
}

__global__ void k_fill(const void* __restrict__ ei) {
    int e  = blockIdx.x * blockDim.x + threadIdx.x;
    int st = gridDim.x * blockDim.x;
    for (; e < NE; e += st) {
        int s = ei_at(ei, e);
        int d = ei_at(ei, (long)NE + e);
        int slot = atomicAdd(&g_cursor[d], 1);
        g_col[slot] = s;
    }
}

// ---- CSR aggregate with optional node-mask and fused BN+ReLU on input ----
// h[n] = f(in[n])*(1-mask[n]) + sum_{s in adj(n), !mask[s]} f(in[s])
// f = BN ? relu(bn(.)) : identity   (mask only if MASKED)
template <int D, bool MASKED, bool BN>
__global__ void k_aggregate(const float* __restrict__ in, float* __restrict__ h,
                            const void* __restrict__ m,
                            const float* __restrict__ gg, const float* __restrict__ bb) {
    const int gtid = blockIdx.x * blockDim.x + threadIdx.x;
    const int warp = gtid >> 5;
    const int lane = gtid & 31;
    if (warp >= NN) return;
    const int D4 = D / 4;
    const float4* ip = (const float4*)in;

    float4 s0 = make_float4(1.f,1.f,1.f,1.f), t0 = make_float4(0.f,0.f,0.f,0.f);
    float4 s1 = s0, t1 = t0;
    if (BN) {
        int ch = lane * 4;
        s0.x = g_rstd[ch+0]*__ldg(&gg[ch+0]); t0.x = __ldg(&bb[ch+0]) - g_mean[ch+0]*s0.x;
        s0.y = g_rstd[ch+1]*__ldg(&gg[ch+1]); t0.y = __ldg(&bb[ch+1]) - g_mean[ch+1]*s0.y;
        s0.z = g_rstd[ch+2]*__ldg(&gg[ch+2]); t0.z = __ldg(&bb[ch+2]) - g_mean[ch+2]*s0.z;
        s0.w = g_rstd[ch+3]*__ldg(&gg[ch+3]); t0.w = __ldg(&bb[ch+3]) - g_mean[ch+3]*s0.w;
        if (D == 256) {
            int c2 = 128 + lane * 4;
            s1.x = g_rstd[c2+0]*__ldg(&gg[c2+0]); t1.x = __ldg(&bb[c2+0]) - g_mean[c2+0]*s1.x;
            s1.y = g_rstd[c2+1]*__ldg(&gg[c2+1]); t1.y = __ldg(&bb[c2+1]) - g_mean[c2+1]*s1.y;
            s1.z = g_rstd[c2+2]*__ldg(&gg[c2+2]); t1.z = __ldg(&bb[c2+2]) - g_mean[c2+2]*s1.z;
            s1.w = g_rstd[c2+3]*__ldg(&gg[c2+3]); t1.w = __ldg(&bb[c2+3]) - g_mean[c2+3]*s1.w;
        }
    }

    float4 a0 = make_float4(0.f,0.f,0.f,0.f), a1 = a0;
    bool selfskip = MASKED && mask_at(m, warp);
    if (!selfskip) {
        float4 v = ip[(size_t)warp * D4 + lane];
        if (BN) {
            v.x = fmaxf(v.x*s0.x + t0.x, 0.f); v.y = fmaxf(v.y*s0.y + t0.y, 0.f);
            v.z = fmaxf(v.z*s0.z + t0.z, 0.f); v.w = fmaxf(v.w*s0.w + t0.w, 0.f);
        }
        a0 = v;
        if (D == 256) {
            float4 w = ip[(size_t)warp * D4 + 32 + lane];
            if (BN) {
                w.x = fmaxf(w.x*s1.x + t1.x, 0.f); w.y = fmaxf(w.y*s1.y + t1.y, 0.f);
                w.z = fmaxf(w.z*s1.z + t1.z, 0.f); w.w = fmaxf(w.w*s1.w + t1.w, 0.f);
            }
            a1 = w;
        }
    }

    int j   = g_rowptr[warp];
    int end = g_rowptr[warp + 1];
    for (; j < end; j++) {
        int s = __ldg(&g_col[j]);
        if (MASKED && mask_at(m, s)) continue;
        float4 v = __ldg(&ip[(size_t)s * D4 + lane]);
        if (BN) {
            v.x = fmaxf(v.x*s0.x + t0.x, 0.f); v.y = fmaxf(v.y*s0.y + t0.y, 0.f);
            v.z = fmaxf(v.z*s0.z + t0.z, 0.f); v.w = fmaxf(v.w*s0.w + t0.w, 0.f);
        }
        a0.x += v.x; a0.y += v.y; a0.z += v.z; a0.w += v.w;
        if (D == 256) {
            float4 w = __ldg(&ip[(size_t)s * D4 + 32 + lane]);
            if (BN) {
                w.x = fmaxf(w.x*s1.x + t1.x, 0.f); w.y = fmaxf(w.y*s1.y + t1.y, 0.f);
                w.z = fmaxf(w.z*s1.z + t1.z, 0.f); w.w = fmaxf(w.w*s1.w + t1.w, 0.f);
            }
            a1.x += w.x; a1.y += w.y; a1.z += w.z; a1.w += w.w;
        }
    }
    float4* hp = (float4*)h;
    hp[(size_t)warp * D4 + lane] = a0;
    if (D == 256) hp[(size_t)warp * D4 + 32 + lane] = a1;
}

// ---------------- bf16 tensor-core GEMM (m16n8k16) with fused BN + stats ----------------
__device__ __forceinline__ uint32_t pack_bf16x2(float lo, float hi) {
    uint32_t r;
    asm("cvt.rn.bf16x2.f32 %0, %1, %2;" : "=r"(r) : "f"(hi), "f"(lo));
    return r;
}

__device__ __forceinline__ void mma_bf16(float* d, const uint32_t* a, const uint32_t* b) {
    asm volatile(
        "mma.sync.aligned.m16n8k16.row.col.f32.bf16.bf16.f32 "
        "{%0,%1,%2,%3}, {%4,%5,%6,%7}, {%8,%9}, {%0,%1,%2,%3};"
        : "+f"(d[0]), "+f"(d[1]), "+f"(d[2]), "+f"(d[3])
        : "r"(a[0]), "r"(a[1]), "r"(a[2]), "r"(a[3]), "r"(b[0]), "r"(b[1]));
}

// C = act(A)[MxK] @ Bt^T, Bt = [N][K] row-major (pre-transposed weights).
// act = identity (BNA=0) or relu(bn(.)) per A-column (BNA=1).
// Epilogue accumulates per-column sum/sumsq of C into g_sum/g_sq.
#define SW 20   // smem row stride in 32-bit words (16 data + 4 pad: conflict-free frags)
template <bool BNA>
__global__ void __launch_bounds__(256)
k_gemm(const float* __restrict__ A, const float* __restrict__ Bt,
       float* __restrict__ C,
       const float* __restrict__ gg, const float* __restrict__ bb,
       int M, int K, int N) {
    __shared__ uint32_t As[128 * SW];
    __shared__ uint32_t Bs[128 * SW];
    __shared__ float s_ps[4][128];
    __shared__ float s_pq[4][128];

    const int tid  = threadIdx.x;
    const int lane = tid & 31;
    const int warp = tid >> 5;
    const int wm   = warp & 3;
    const int wn   = warp >> 2;
    const int gid  = lane >> 2;
    const int tq   = lane & 3;
    const int brow = blockIdx.y * 128;
    const int bcol = blockIdx.x * 128;

    float acc[2][8][4];
    #pragma unroll
    for (int i = 0; i < 2; i++)
        #pragma unroll
        for (int j = 0; j < 8; j++)
            #pragma unroll
            for (int q = 0; q < 4; q++) acc[i][j][q] = 0.f;

    for (int k0 = 0; k0 < K; k0 += 32) {
        #pragma unroll
        for (int i = 0; i < 4; i++) {
            int idx = tid + i * 256;       // 0..1023
            int row = idx >> 3;            // 0..127
            int k8  = (idx & 7) << 2;      // 0,4,...,28
            // A tile (bf16, BN-fused, bounds on M)
            float4 v = make_float4(0.f, 0.f, 0.f, 0.f);
            int gr = brow + row;
            if (gr < M) {
                v = *(const float4*)(A + (size_t)gr * K + k0 + k8);
                if (BNA) {
                    int ch = k0 + k8;
                    v.x = fmaxf((v.x - g_mean[ch+0]) * g_rstd[ch+0] * __ldg(&gg[ch+0]) + __ldg(&bb[ch+0]), 0.f);
                    v.y = fmaxf((v.y - g_mean[ch+1]) * g_rstd[ch+1] * __ldg(&gg[ch+1]) + __ldg(&bb[ch+1]), 0.f);
                    v.z = fmaxf((v.z - g_mean[ch+2]) * g_rstd[ch+2] * __ldg(&gg[ch+2]) + __ldg(&bb[ch+2]), 0.f);
                    v.w = fmaxf((v.w - g_mean[ch+3]) * g_rstd[ch+3] * __ldg(&gg[ch+3]) + __ldg(&bb[ch+3]), 0.f);
                }
            }
            *(uint2*)&As[row * SW + (k8 >> 1)] =
                make_uint2(pack_bf16x2(v.x, v.y), pack_bf16x2(v.z, v.w));
            // B tile from transposed weights [N][K]
            float4 w = *(const float4*)(Bt + (size_t)(bcol + row) * K + k0 + k8);
            *(uint2*)&Bs[row * SW + (k8 >> 1)] =
                make_uint2(pack_bf16x2(w.x, w.y), pack_bf16x2(w.z, w.w));
        }
        __syncthreads();

        #pragma unroll
        for (int kw = 0; kw < 16; kw += 8) {     // two k16 steps
            uint32_t a[2][4], b[8][2];
            #pragma unroll
            for (int mt = 0; mt < 2; mt++) {
                int r = wm * 32 + mt * 16 + gid;
                a[mt][0] = As[r * SW + kw + tq];
                a[mt][1] = As[(r + 8) * SW + kw + tq];
                a[mt][2] = As[r * SW + kw + tq + 4];
                a[mt][3] = As[(r + 8) * SW + kw + tq + 4];
            }
            #pragma unroll
            for (int nt = 0; nt < 8; nt++) {
                int cn = wn * 64 + nt * 8 + gid;
                b[nt][0] = Bs[cn * SW + kw + tq];
                b[nt][1] = Bs[cn * SW + kw + tq + 4];
            }
            #pragma unroll
            for (int mt = 0; mt < 2; mt++)
                #pragma unroll
                for (int nt = 0; nt < 8; nt++)
                    mma_bf16(acc[mt][nt], a[mt], b[nt]);
        }
        __syncthreads();
    }

    // ---- store C ----
    #pragma unroll
    for (int mt = 0; mt < 2; mt++) {
        int r0 = brow + wm * 32 + mt * 16 + gid;
        int r1 = r0 + 8;
        #pragma unroll
        for (int nt = 0; nt < 8; nt++) {
            int c = bcol + wn * 64 + nt * 8 + tq * 2;
            if (r0 < M)
                *(float2*)(C + (size_t)r0 * N + c) = make_float2(acc[mt][nt][0], acc[mt][nt][1]);
            if (r1 < M)
                *(float2*)(C + (size_t)r1 * N + c) = make_float2(acc[mt][nt][2], acc[mt][nt][3]);
        }
    }

    // ---- column stats: shuffle over gid lanes, conflict-free smem, 1 atomic/col ----
    float csum[16], csq[16];
    #pragma unroll
    for (int nt = 0; nt < 8; nt++) {
        float s0 = 0.f, s1 = 0.f, q0 = 0.f, q1 = 0.f;
        #pragma unroll
        for (int mt = 0; mt < 2; mt++) {
            int r0 = brow + wm * 32 + mt * 16 + gid;
            int r1 = r0 + 8;
            if (r0 < M) {
                float a = acc[mt][nt][0], b = acc[mt][nt][1];
                s0 += a; q0 += a * a; s1 += b; q1 += b * b;
            }
            if (r1 < M) {
                float a = acc[mt][nt][2], b = acc[mt][nt][3];
                s0 += a; q0 += a * a; s1 += b; q1 += b * b;
            }
        }
        csum[nt * 2] = s0; csum[nt * 2 + 1] = s1;
        csq [nt * 2] = q0; csq [nt * 2 + 1] = q1;
    }
    #pragma unroll
    for (int o = 4; o <= 16; o <<= 1) {
        #pragma unroll
        for (int p = 0; p < 16; p++) {
            csum[p] += __shfl_xor_sync(0xffffffffu, csum[p], o);
            csq[p]  += __shfl_xor_sync(0xffffffffu, csq[p],  o);
        }
    }
    if (gid == 0) {
        #pragma unroll
        for (int nt = 0; nt < 8; nt++) {
            int lc = wn * 64 + nt * 8 + tq * 2;
            s_ps[wm][lc]     = csum[nt * 2];
            s_ps[wm][lc + 1] = csum[nt * 2 + 1];
            s_pq[wm][lc]     = csq[nt * 2];
            s_pq[wm][lc + 1] = csq[nt * 2 + 1];
        }
    }
    __syncthreads();
    if (tid < 128) {
        float ts = s_ps[0][tid] + s_ps[1][tid] + s_ps[2][tid] + s_ps[3][tid];
        float tg = s_pq[0][tid] + s_pq[1][tid] + s_pq[2][tid] + s_pq[3][tid];
        atomicAdd(&g_sum[bcol + tid], (double)ts);
        atomicAdd(&g_sq[bcol + tid],  (double)tg);
    }
}

__global__ void k_bn_fin(int C) {
    int c = threadIdx.x;
    if (c < C) {
        double mu  = g_sum[c] / NN;
        double var = g_sq[c] / NN - mu * mu;
        if (var < 0.0) var = 0.0;
        g_mean[c] = (float)mu;
        g_rstd[c] = (float)rsqrt(var + 1e-5);
    }
    if (c < D_HID) { g_sum[c] = 0.0; g_sq[c] = 0.0; }
}

__global__ void k_bn_apply(const float* __restrict__ in, float* __restrict__ out,
                           const float* __restrict__ gg, const float* __restrict__ bb,
                           int cmask, long total) {
    long i  = blockIdx.x * (long)blockDim.x + threadIdx.x;
    long st = (long)gridDim.x * blockDim.x;
    for (; i < total; i += st) {
        int c   = (int)(i & cmask);
        float v = (in[i] - g_mean[c]) * g_rstd[c] * __ldg(&gg[c]) + __ldg(&bb[c]);
        out[i] = v > 0.f ? v : 0.f;
    }
}

// ---------------- cosine losses (D = 128, one warp per node) ----------------
__global__ void k_cos(const float* __restrict__ a, const float* __restrict__ b,
                      const void* __restrict__ m, int useMask, int accOff) {
    int gtid = blockIdx.x * blockDim.x + threadIdx.x;
    int warp = gtid >> 5, lane = gtid & 31;
    int nw   = (gridDim.x * blockDim.x) >> 5;
    double ls = 0.0, lc = 0.0;
    for (int n = warp; n < NN; n += nw) {
        if (useMask && !mask_at(m, n)) continue;
        float4 va = *((const float4*)(a + (size_t)n * 128) + lane);
        float4 vb = *((const float4*)(b + (size_t)n * 128) + lane);
        float dot = va.x * vb.x + va.y * vb.y + va.z * vb.z + va.w * vb.w;
        float na  = va.x * va.x + va.y * va.y + va.z * va.z + va.w * va.w;
        float nb  = vb.x * vb.x + vb.y * vb.y + vb.z * vb.z + vb.w * vb.w;
        #pragma unroll
        for (int o = 16; o; o >>= 1) {
            dot += __shfl_xor_sync(0xffffffffu, dot, o);
            na  += __shfl_xor_sync(0xffffffffu, na,  o);
            nb  += __shfl_xor_sync(0xffffffffu, nb,  o);
        }
        if (lane == 0) {
            float cs = dot / (fmaxf(sqrtf(na), 1e-12f) * fmaxf(sqrtf(nb), 1e-12f));
            ls += 1.0 - (double)cs;
            lc += 1.0;
        }
    }
    if (lane == 0) {
        atomicAdd(&g_acc[accOff], ls);
        if (useMask) atomicAdd(&g_acc[accOff + 1], lc);
    }
}

__global__ void k_finalize(float* out) {
    double v = g_acc[0] / g_acc[1] + g_acc[2] / g_acc[3] + 0.1 * (g_acc[4] / (double)NN);
    out[0] = (float)v;
}

// ---------------- host-side orchestration ----------------
extern "C" void kernel_launch(void* const* d_in, const int* in_sizes, int n_in,
                              void* d_out, int out_size) {
    const float* x   = (const float*)d_in[0];
    const void*  ei1 = d_in[1];
    const void*  ei2 = d_in[2];
    const void*  m1  = d_in[3];
    const void*  m2  = d_in[4];
    // d_in[5] = batch : dead code in the reference
    const float* e0_w1 = (const float*)d_in[6];
    const float* e0_w2 = (const float*)d_in[7];
    const float* e0_bg = (const float*)d_in[8];
    const float* e0_bb = (const float*)d_in[9];
    const float* e0_ng = (const float*)d_in[10];
    const float* e0_nb = (const float*)d_in[11];
    const float* e1_w1 = (const float*)d_in[12];
    const float* e1_w2 = (const float*)d_in[13];
    const float* e1_bg = (const float*)d_in[14];
    const float* e1_bb = (const float*)d_in[15];
    const float* e1_ng = (const float*)d_in[16];
    const float* e1_nb = (const float*)d_in[17];
    const float* d_w1  = (const float*)d_in[18];
    const float* d_w2  = (const float*)d_in[19];
    const float* d_bg  = (const float*)d_in[20];
    const float* d_bb  = (const float*)d_in[21];
    const float* d_ng  = (const float*)d_in[22];
    const float* d_nb  = (const float*)d_in[23];
    float* out = (float*)d_out;

    float *H, *T, *U, *RE1, *RE2, *WT;
    cudaGetSymbolAddress((void**)&H,   g_H);
    cudaGetSymbolAddress((void**)&T,   g_T);
    cudaGetSymbolAddress((void**)&U,   g_U);
    cudaGetSymbolAddress((void**)&RE1, g_RE1);
    cudaGetSymbolAddress((void**)&RE2, g_RE2);
    cudaGetSymbolAddress((void**)&WT,  g_WT);

    // transposed-weight arena offsets
    float* WT0 = WT;            // e0_w1: [512][128]
    float* WT1 = WT + 65536;    // e0_w2: [256][512]
    float* WT2 = WT + 196608;   // e1_w1: [512][256]
    float* WT3 = WT + 327680;   // e1_w2: [256][512]
    float* WT4 = WT + 458752;   // d_w1 : [512][256]
    float* WT5 = WT + 589824;   // d_w2 : [128][512]

    // dtype auto-detection
    k_zero_cnt<<<1, 32>>>();
    k_detect<<<128, 256>>>((const unsigned char*)m1, (const int*)ei1);
    k_detect_fin<<<1, 32>>>();
    k_zero_acc<<<2, 256>>>();

    // weight transposes (once)
    dim3 tb(32, 8);
    k_transpose<<<dim3(512/32, 128/32), tb>>>(e0_w1, WT0, 128, 512);
    k_transpose<<<dim3(256/32, 512/32), tb>>>(e0_w2, WT1, 512, 256);
    k_transpose<<<dim3(512/32, 256/32), tb>>>(e1_w1, WT2, 256, 512);
    k_transpose<<<dim3(256/32, 512/32), tb>>>(e1_w2, WT3, 512, 256);
    k_transpose<<<dim3(512/32, 256/32), tb>>>(d_w1,  WT4, 256, 512);
    k_transpose<<<dim3(128/32, 512/32), tb>>>(d_w2,  WT5, 512, 128);

    const int AGG_BLK = (NN * 32 + 255) / 256;
    const dim3 gN512(4, (NN + 127) / 128);
    const dim3 gN256(2, (NN + 127) / 128);
    const dim3 gN128(1, (NN + 127) / 128);

    for (int pass = 0; pass < 2; pass++) {
        const void* ei = pass == 0 ? ei1 : ei2;
        const void* m  = pass == 0 ? m1  : m2;
        float*      RE = pass == 0 ? RE1 : RE2;

        // CSR for this pass (shared by all 3 layers)
        k_zero_deg<<<256, 256>>>();
        k_count<<<1024, 256>>>(ei);
        k_scan<<<1, 1024>>>();
        k_fill<<<1024, 256>>>(ei);

        // ---- encoder layer 0: agg(mask(x)) -> T -> U ----
        k_aggregate<128, true, false><<<AGG_BLK, 256>>>(x, H, m, nullptr, nullptr);
        k_gemm<false><<<gN512, 256>>>(H, WT0, T, nullptr, nullptr, NN, 128, 512);
        k_bn_fin<<<1, 512>>>(512);
        k_gemm<true><<<gN256, 256>>>(T, WT1, U, e0_bg, e0_bb, NN, 512, 256);
        k_bn_fin<<<1, 512>>>(256);

        // ---- encoder layer 1: agg(bnrelu(U)) -> T -> U ----
        k_aggregate<256, false, true><<<AGG_BLK, 256>>>(U, H, nullptr, e0_ng, e0_nb);
        k_gemm<false><<<gN512, 256>>>(H, WT2, T, nullptr, nullptr, NN, 256, 512);
        k_bn_fin<<<1, 512>>>(512);
        k_gemm<true><<<gN256, 256>>>(T, WT3, U, e1_bg, e1_bb, NN, 512, 256);
        k_bn_fin<<<1, 512>>>(256);

        // ---- decoder: agg(mask(bnrelu(U))) -> T -> U(128) -> RE ----
        k_aggregate<256, true, true><<<AGG_BLK, 256>>>(U, H, m, e1_ng, e1_nb);
        k_gemm<false><<<gN512, 256>>>(H, WT4, T, nullptr, nullptr, NN, 256, 512);
        k_bn_fin<<<1, 512>>>(512);
        k_gemm<true><<<gN128, 256>>>(T, WT5, U, d_bg, d_bb, NN, 512, 128);
        k_bn_fin<<<1, 512>>>(128);
        k_bn_apply<<<4096, 256>>>(U, RE, d_ng, d_nb, 127, (long)NN * 128);

        // masked reconstruction loss
        k_cos<<<512, 256>>>(RE, x, m, 1, pass * 2);
    }

    // contrastive term over all nodes
    k_cos<<<512, 256>>>(RE2, RE1, nullptr, 0, 4);
    k_finalize<<<1, 1>>>(out);
    (void)in_sizes; (void)n_in; (void)out_size;
}

// round 8
// speedup vs baseline: 3.9948x; 1.3970x over previous
#include <cuda_runtime.h>
#include <cuda_bf16.h>
#include <math.h>
#include <stdint.h>

#define NN    50000
#define MPAD  50048
#define NE    320000
#define D_IN  128
#define D_OUT 256
#define D_HID 512

// ---------------- scratch (static device globals; no allocation) ----------------
__device__ __nv_bfloat16 g_Hb[(size_t)MPAD * D_OUT];   // bf16 GEMM-A input (agg out)
__device__ __nv_bfloat16 g_Tb[(size_t)MPAD * D_HID];   // bf16 hidden (GEMM1 out)
__device__ __nv_bfloat16 g_WTb[655360];                // bf16 transposed weights
__device__ float  g_U  [(size_t)NN * D_OUT];
__device__ float  g_RE1[(size_t)NN * D_IN];
__device__ float  g_RE2[(size_t)NN * D_IN];
__device__ double g_sum[D_HID];
__device__ double g_sq [D_HID];
__device__ float  g_mean[D_HID];
__device__ float  g_rstd[D_HID];
__device__ double g_acc[8];

// CSR scratch
__device__ int g_deg   [NN];
__device__ int g_rowptr[NN + 1];
__device__ int g_cursor[NN];
__device__ int g_col   [NE];

__device__ int g_mask_mode, g_ei_i64, g_cnt[8];

// ---------------- dtype detection ----------------
__global__ void k_zero_cnt() { if (threadIdx.x < 8) g_cnt[threadIdx.x] = 0; }

__global__ void k_detect(const unsigned char* __restrict__ mbytes,
                         const int* __restrict__ eints) {
    int i  = blockIdx.x * blockDim.x + threadIdx.x;
    int st = gridDim.x * blockDim.x;
    int c1 = 0, c3 = 0, ez = 0;
    for (int j = i; j < NN; j += st) {
        unsigned char v = mbytes[j];
        if (v && (j & 3) == 1) c1++;
        if (v && (j & 3) == 3) c3++;
    }
    for (int j = i; j < 100000; j += st)
        if ((j & 1) && eints[j] == 0) ez++;
    atomicAdd(&g_cnt[0], c1);
    atomicAdd(&g_cnt[1], c3);
    atomicAdd(&g_cnt[2], ez);
}

__global__ void k_detect_fin() {
    if (threadIdx.x == 0) {
        if      (g_cnt[1] > 1000) g_mask_mode = 2;
        else if (g_cnt[0] > 1000) g_mask_mode = 0;
        else                      g_mask_mode = 1;
        g_ei_i64 = (g_cnt[2] > 25000) ? 1 : 0;
    }
}

__device__ __forceinline__ bool mask_at(const void* __restrict__ m, int n) {
    int mode = g_mask_mode;
    if (mode == 0) return ((const unsigned char*)m)[n] != 0;
    if (mode == 1) return ((const int*)m)[n] != 0;
    return ((const float*)m)[n] != 0.f;
}

__device__ __forceinline__ int ei_at(const void* __restrict__ ei, long idx) {
    return g_ei_i64 ? (int)((const long long*)ei)[idx] : ((const int*)ei)[idx];
}

// ---------------- tiny utility kernels ----------------
__global__ void k_zero_acc() {
    if (threadIdx.x < 8 && blockIdx.x == 0) g_acc[threadIdx.x] = 0.0;
    int c = blockIdx.x * blockDim.x + threadIdx.x;
    if (c < D_HID) { g_sum[c] = 0.0; g_sq[c] = 0.0; }
}

// ---------------- weight transpose+convert: W[K][N] f32 -> WT[N][K] bf16 ----------------
__global__ void k_transpose(const float* __restrict__ W, __nv_bfloat16* __restrict__ WT,
                            int K, int N) {
    __shared__ float tile[32][33];
    int n0 = blockIdx.x * 32, k0 = blockIdx.y * 32;
    int tx = threadIdx.x, ty = threadIdx.y;
    #pragma unroll
    for (int i = 0; i < 4; i++)
        tile[ty + i * 8][tx] = W[(size_t)(k0 + ty + i * 8) * N + n0 + tx];
    __syncthreads();
    #pragma unroll
    for (int i = 0; i < 4; i++)
        WT[(size_t)(n0 + ty + i * 8) * K + k0 + tx] = __float2bfloat16(tile[tx][ty + i * 8]);
}

// ---------------- CSR build ----------------
__global__ void k_zero_deg() {
    int i  = blockIdx.x * blockDim.x + threadIdx.x;
    int st = gridDim.x * blockDim.x;
    for (; i < NN; i += st) g_deg[i] = 0;
}

__global__ void k_count(const void* __restrict__ ei) {
    int e  = blockIdx.x * blockDim.x + threadIdx.x;
    int st = gridDim.x * blockDim.x;
    for (; e < NE; e += st)
        atomicAdd(&g_deg[ei_at(ei, (long)NE + e)], 1);
}

__global__ void __launch_bounds__(1024) k_scan() {
    __shared__ int ssum[1024];
    const int t = threadIdx.x;
    const int C = (NN + 1023) / 1024;
    int lo = t * C, hi = min(NN, lo + C);
    int s = 0;
    for (int i = lo; i < hi; i++) s += g_deg[i];
    ssum[t] = s;
    __syncthreads();
    #pragma unroll
    for (int o = 1; o < 1024; o <<= 1) {
        int v = (t >= o) ? ssum[t - o] : 0;
        __syncthreads();
        ssum[t] += v;
        __syncthreads();
    }
    int run = (t == 0) ? 0 : ssum[t - 1];
    for (int i = lo; i < hi; i++) {
        int d = g_deg[i];
        g_rowptr[i] = run;
        g_cursor[i] = run;
        run += d;
    }
    if (t == 1023) g_rowptr[NN] = run;
}

__global__ void k_fill(const void* __restrict__ ei) {
    int e  = blockIdx.x * blockDim.x + threadIdx.x;
    int st = gridDim.x * blockDim.x;
    for (; e < NE; e += st) {
        int s = ei_at(ei, e);
        int d = ei_at(ei, (long)NE + e);
        int slot = atomicAdd(&g_cursor[d], 1);
        g_col[slot] = s;
    }
}

// ---------------- bf16 pack helpers ----------------
__device__ __forceinline__ uint32_t pack_bf16x2(float lo, float hi) {
    uint32_t r;
    asm("cvt.rn.bf16x2.f32 %0, %1, %2;" : "=r"(r) : "f"(hi), "f"(lo));
    return r;
}

// ---- CSR aggregate (fp32 in, bf16 out), optional mask + fused BN+ReLU ----
template <int D, bool MASKED, bool BN>
__global__ void k_aggregate(const float* __restrict__ in, __nv_bfloat16* __restrict__ hb,
                            const void* __restrict__ m,
                            const float* __restrict__ gg, const float* __restrict__ bb) {
    const int gtid = blockIdx.x * blockDim.x + threadIdx.x;
    const int warp = gtid >> 5;
    const int lane = gtid & 31;
    if (warp >= NN) return;
    const int D4 = D / 4;
    const float4* ip = (const float4*)in;

    float4 s0 = make_float4(1.f,1.f,1.f,1.f), t0 = make_float4(0.f,0.f,0.f,0.f);
    float4 s1 = s0, t1 = t0;
    if (BN) {
        int ch = lane * 4;
        s0.x = g_rstd[ch+0]*__ldg(&gg[ch+0]); t0.x = __ldg(&bb[ch+0]) - g_mean[ch+0]*s0.x;
        s0.y = g_rstd[ch+1]*__ldg(&gg[ch+1]); t0.y = __ldg(&bb[ch+1]) - g_mean[ch+1]*s0.y;
        s0.z = g_rstd[ch+2]*__ldg(&gg[ch+2]); t0.z = __ldg(&bb[ch+2]) - g_mean[ch+2]*s0.z;
        s0.w = g_rstd[ch+3]*__ldg(&gg[ch+3]); t0.w = __ldg(&bb[ch+3]) - g_mean[ch+3]*s0.w;
        if (D == 256) {
            int c2 = 128 + lane * 4;
            s1.x = g_rstd[c2+0]*__ldg(&gg[c2+0]); t1.x = __ldg(&bb[c2+0]) - g_mean[c2+0]*s1.x;
            s1.y = g_rstd[c2+1]*__ldg(&gg[c2+1]); t1.y = __ldg(&bb[c2+1]) - g_mean[c2+1]*s1.y;
            s1.z = g_rstd[c2+2]*__ldg(&gg[c2+2]); t1.z = __ldg(&bb[c2+2]) - g_mean[c2+2]*s1.z;
            s1.w = g_rstd[c2+3]*__ldg(&gg[c2+3]); t1.w = __ldg(&bb[c2+3]) - g_mean[c2+3]*s1.w;
        }
    }

    float4 a0 = make_float4(0.f,0.f,0.f,0.f), a1 = a0;
    auto bnrelu0 = [&](float4 v) {
        if (BN) {
            v.x = fmaxf(v.x*s0.x + t0.x, 0.f); v.y = fmaxf(v.y*s0.y + t0.y, 0.f);
            v.z = fmaxf(v.z*s0.z + t0.z, 0.f); v.w = fmaxf(v.w*s0.w + t0.w, 0.f);
        }
        return v;
    };
    auto bnrelu1 = [&](float4 v) {
        if (BN) {
            v.x = fmaxf(v.x*s1.x + t1.x, 0.f); v.y = fmaxf(v.y*s1.y + t1.y, 0.f);
            v.z = fmaxf(v.z*s1.z + t1.z, 0.f); v.w = fmaxf(v.w*s1.w + t1.w, 0.f);
        }
        return v;
    };

    if (!(MASKED && mask_at(m, warp))) {
        float4 v = bnrelu0(ip[(size_t)warp * D4 + lane]);
        a0 = v;
        if (D == 256) a1 = bnrelu1(ip[(size_t)warp * D4 + 32 + lane]);
    }

    int j   = g_rowptr[warp];
    int end = g_rowptr[warp + 1];
    // 4-way batched neighbor gather for MLP
    for (; j < end; j += 4) {
        int cnt = end - j;
        int idx[4]; bool ok[4];
        #pragma unroll
        for (int t = 0; t < 4; t++) {
            idx[t] = (t < cnt) ? __ldg(&g_col[j + t]) : 0;
            ok[t]  = (t < cnt) && (!MASKED || !mask_at(m, idx[t]));
        }
        float4 v[4], w[4];
        #pragma unroll
        for (int t = 0; t < 4; t++) {
            if (ok[t]) {
                v[t] = __ldg(&ip[(size_t)idx[t] * D4 + lane]);
                if (D == 256) w[t] = __ldg(&ip[(size_t)idx[t] * D4 + 32 + lane]);
            }
        }
        #pragma unroll
        for (int t = 0; t < 4; t++) {
            if (ok[t]) {
                float4 p = bnrelu0(v[t]);
                a0.x += p.x; a0.y += p.y; a0.z += p.z; a0.w += p.w;
                if (D == 256) {
                    float4 q = bnrelu1(w[t]);
                    a1.x += q.x; a1.y += q.y; a1.z += q.z; a1.w += q.w;
                }
            }
        }
    }

    uint2* hp = (uint2*)hb;   // 4 bf16 per lane-slot
    hp[(size_t)warp * (D / 4) + lane] = make_uint2(pack_bf16x2(a0.x, a0.y), pack_bf16x2(a0.z, a0.w));
    if (D == 256)
        hp[(size_t)warp * (D / 4) + 32 + lane] = make_uint2(pack_bf16x2(a1.x, a1.y), pack_bf16x2(a1.z, a1.w));
}

// ---------------- cp.async helpers ----------------
__device__ __forceinline__ void cp_async16(uint32_t dst, const void* src) {
    asm volatile("cp.async.cg.shared.global [%0], [%1], 16;" :: "r"(dst), "l"(src));
}
__device__ __forceinline__ void cp_commit() { asm volatile("cp.async.commit_group;"); }
template <int W> __device__ __forceinline__ void cp_wait() {
    asm volatile("cp.async.wait_group %0;" :: "n"(W));
}

// ---------------- bf16 mma ----------------
__device__ __forceinline__ void mma_bf16(float* d, const uint32_t* a, const uint32_t* b) {
    asm volatile(
        "mma.sync.aligned.m16n8k16.row.col.f32.bf16.bf16.f32 "
        "{%0,%1,%2,%3}, {%4,%5,%6,%7}, {%8,%9}, {%0,%1,%2,%3};"
        : "+f"(d[0]), "+f"(d[1]), "+f"(d[2]), "+f"(d[3])
        : "r"(a[0]), "r"(a[1]), "r"(a[2]), "r"(a[3]), "r"(b[0]), "r"(b[1]));
}

// ---------------- pipelined bf16 GEMM: C = A[M_PAD x K]bf16 @ Bt[N x K]bf16^T ----------------
// cp.async double-buffered; epilogue: per-column sum/sumsq -> g_sum/g_sq.
// WBF16: write C as bf16 into Cb, else fp32 into C.
#define SW 20
template <bool WBF16>
__global__ void __launch_bounds__(256)
k_gemm(const __nv_bfloat16* __restrict__ A, const __nv_bfloat16* __restrict__ Bt,
       float* __restrict__ C, __nv_bfloat16* __restrict__ Cb,
       int M, int K, int N) {
    __shared__ uint32_t As[2][128 * SW];
    __shared__ uint32_t Bs[2][128 * SW];
    __shared__ float s_ps[4][128];
    __shared__ float s_pq[4][128];

    const int tid  = threadIdx.x;
    const int lane = tid & 31;
    const int warp = tid >> 5;
    const int wm   = warp & 3;
    const int wn   = warp >> 2;
    const int gid  = lane >> 2;
    const int tq   = lane & 3;
    const int brow = blockIdx.y * 128;
    const int bcol = blockIdx.x * 128;

    uint32_t asb[2] = { (uint32_t)__cvta_generic_to_shared(&As[0][0]),
                        (uint32_t)__cvta_generic_to_shared(&As[1][0]) };
    uint32_t bsb[2] = { (uint32_t)__cvta_generic_to_shared(&Bs[0][0]),
                        (uint32_t)__cvta_generic_to_shared(&Bs[1][0]) };

    float acc[2][8][4];
    #pragma unroll
    for (int i = 0; i < 2; i++)
        #pragma unroll
        for (int j = 0; j < 8; j++)
            #pragma unroll
            for (int q = 0; q < 4; q++) acc[i][j][q] = 0.f;

    const int nch = K >> 5;   // 32 bf16 per chunk

    auto fill = [&](int buf, int k0) {
        #pragma unroll
        for (int i = 0; i < 2; i++) {
            int idx = tid + i * 256;          // 0..511
            int row = idx >> 2;               // 0..127
            int c16 = idx & 3;                // 16B chunk within 64B row-slice
            uint32_t doff = (uint32_t)(row * SW + c16 * 4) * 4;
            cp_async16(asb[buf] + doff, A  + (size_t)(brow + row) * K + k0 + c16 * 8);
            cp_async16(bsb[buf] + doff, Bt + (size_t)(bcol + row) * K + k0 + c16 * 8);
        }
    };

    fill(0, 0);
    cp_commit();

    for (int c = 0; c < nch; c++) {
        const int buf = c & 1;
        if (c + 1 < nch) {
            fill(1 - buf, (c + 1) << 5);
            cp_commit();
            cp_wait<1>();
        } else {
            cp_wait<0>();
        }
        __syncthreads();

        #pragma unroll
        for (int kw = 0; kw < 16; kw += 8) {
            uint32_t a[2][4], b[8][2];
            #pragma unroll
            for (int mt = 0; mt < 2; mt++) {
                int r = wm * 32 + mt * 16 + gid;
                a[mt][0] = As[buf][r * SW + kw + tq];
                a[mt][1] = As[buf][(r + 8) * SW + kw + tq];
                a[mt][2] = As[buf][r * SW + kw + tq + 4];
                a[mt][3] = As[buf][(r + 8) * SW + kw + tq + 4];
            }
            #pragma unroll
            for (int nt = 0; nt < 8; nt++) {
                int cn = wn * 64 + nt * 8 + gid;
                b[nt][0] = Bs[buf][cn * SW + kw + tq];
                b[nt][1] = Bs[buf][cn * SW + kw + tq + 4];
            }
            #pragma unroll
            for (int mt = 0; mt < 2; mt++)
                #pragma unroll
                for (int nt = 0; nt < 8; nt++)
                    mma_bf16(acc[mt][nt], a[mt], b[nt]);
        }
        __syncthreads();
    }

    // ---- store C ----
    #pragma unroll
    for (int mt = 0; mt < 2; mt++) {
        int r0 = brow + wm * 32 + mt * 16 + gid;
        int r1 = r0 + 8;
        #pragma unroll
        for (int nt = 0; nt < 8; nt++) {
            int c = bcol + wn * 64 + nt * 8 + tq * 2;
            if (WBF16) {
                if (r0 < M)
                    *(uint32_t*)(Cb + (size_t)r0 * N + c) = pack_bf16x2(acc[mt][nt][0], acc[mt][nt][1]);
                if (r1 < M)
                    *(uint32_t*)(Cb + (size_t)r1 * N + c) = pack_bf16x2(acc[mt][nt][2], acc[mt][nt][3]);
            } else {
                if (r0 < M)
                    *(float2*)(C + (size_t)r0 * N + c) = make_float2(acc[mt][nt][0], acc[mt][nt][1]);
                if (r1 < M)
                    *(float2*)(C + (size_t)r1 * N + c) = make_float2(acc[mt][nt][2], acc[mt][nt][3]);
            }
        }
    }

    // ---- column stats ----
    float csum[16], csq[16];
    #pragma unroll
    for (int nt = 0; nt < 8; nt++) {
        float s0 = 0.f, s1 = 0.f, q0 = 0.f, q1 = 0.f;
        #pragma unroll
        for (int mt = 0; mt < 2; mt++) {
            int r0 = brow + wm * 32 + mt * 16 + gid;
            int r1 = r0 + 8;
            if (r0 < M) {
                float a = acc[mt][nt][0], b = acc[mt][nt][1];
                s0 += a; q0 += a * a; s1 += b; q1 += b * b;
            }
            if (r1 < M) {
                float a = acc[mt][nt][2], b = acc[mt][nt][3];
                s0 += a; q0 += a * a; s1 += b; q1 += b * b;
            }
        }
        csum[nt * 2] = s0; csum[nt * 2 + 1] = s1;
        csq [nt * 2] = q0; csq [nt * 2 + 1] = q1;
    }
    #pragma unroll
    for (int o = 4; o <= 16; o <<= 1) {
        #pragma unroll
        for (int p = 0; p < 16; p++) {
            csum[p] += __shfl_xor_sync(0xffffffffu, csum[p], o);
            csq[p]  += __shfl_xor_sync(0xffffffffu, csq[p],  o);
        }
    }
    if (gid == 0) {
        #pragma unroll
        for (int nt = 0; nt < 8; nt++) {
            int lc = wn * 64 + nt * 8 + tq * 2;
            s_ps[wm][lc]     = csum[nt * 2];
            s_ps[wm][lc + 1] = csum[nt * 2 + 1];
            s_pq[wm][lc]     = csq[nt * 2];
            s_pq[wm][lc + 1] = csq[nt * 2 + 1];
        }
    }
    __syncthreads();
    if (tid < 128) {
        float ts = s_ps[0][tid] + s_ps[1][tid] + s_ps[2][tid] + s_ps[3][tid];
        float tg = s_pq[0][tid] + s_pq[1][tid] + s_pq[2][tid] + s_pq[3][tid];
        atomicAdd(&g_sum[bcol + tid], (double)ts);
        atomicAdd(&g_sq[bcol + tid],  (double)tg);
    }
}

__global__ void k_bn_fin(int C) {
    int c = threadIdx.x;
    if (c < C) {
        double mu  = g_sum[c] / NN;
        double var = g_sq[c] / NN - mu * mu;
        if (var < 0.0) var = 0.0;
        g_mean[c] = (float)mu;
        g_rstd[c] = (float)rsqrt(var + 1e-5);
    }
    if (c < D_HID) { g_sum[c] = 0.0; g_sq[c] = 0.0; }
}

// in-place bf16 BN+ReLU over Tb (channel pairs; cpmask = C/2 - 1)
__global__ void k_bnrelu_b(__nv_bfloat162* __restrict__ t,
                           const float* __restrict__ gg, const float* __restrict__ bb,
                           int cpmask, long totalPairs) {
    long i  = blockIdx.x * (long)blockDim.x + threadIdx.x;
    long st = (long)gridDim.x * blockDim.x;
    for (; i < totalPairs; i += st) {
        int c = (int)(i & cpmask) * 2;
        float sx = g_rstd[c]     * __ldg(&gg[c]);
        float sy = g_rstd[c + 1] * __ldg(&gg[c + 1]);
        float tx = __ldg(&bb[c])     - g_mean[c]     * sx;
        float ty = __ldg(&bb[c + 1]) - g_mean[c + 1] * sy;
        __nv_bfloat162 v = t[i];
        float a = fmaxf(__bfloat162float(v.x) * sx + tx, 0.f);
        float b = fmaxf(__bfloat162float(v.y) * sy + ty, 0.f);
        uint32_t p = pack_bf16x2(a, b);
        t[i] = *(__nv_bfloat162*)&p;
    }
}

// fp32 BN+ReLU (decoder output)
__global__ void k_bn_apply(const float* __restrict__ in, float* __restrict__ out,
                           const float* __restrict__ gg, const float* __restrict__ bb,
                           int cmask, long total) {
    long i  = blockIdx.x * (long)blockDim.x + threadIdx.x;
    long st = (long)gridDim.x * blockDim.x;
    for (; i < total; i += st) {
        int c   = (int)(i & cmask);
        float v = (in[i] - g_mean[c]) * g_rstd[c] * __ldg(&gg[c]) + __ldg(&bb[c]);
        out[i] = v > 0.f ? v : 0.f;
    }
}

// ---------------- cosine losses ----------------
__global__ void k_cos(const float* __restrict__ a, const float* __restrict__ b,
                      const void* __restrict__ m, int useMask, int accOff) {
    int gtid = blockIdx.x * blockDim.x + threadIdx.x;
    int warp = gtid >> 5, lane = gtid & 31;
    int nw   = (gridDim.x * blockDim.x) >> 5;
    double ls = 0.0, lc = 0.0;
    for (int n = warp; n < NN; n += nw) {
        if (useMask && !mask_at(m, n)) continue;
        float4 va = *((const float4*)(a + (size_t)n * 128) + lane);
        float4 vb = *((const float4*)(b + (size_t)n * 128) + lane);
        float dot = va.x * vb.x + va.y * vb.y + va.z * vb.z + va.w * vb.w;
        float na  = va.x * va.x + va.y * va.y + va.z * va.z + va.w * va.w;
        float nb  = vb.x * vb.x + vb.y * vb.y + vb.z * vb.z + vb.w * vb.w;
        #pragma unroll
        for (int o = 16; o; o >>= 1) {
            dot += __shfl_xor_sync(0xffffffffu, dot, o);
            na  += __shfl_xor_sync(0xffffffffu, na,  o);
            nb  += __shfl_xor_sync(0xffffffffu, nb,  o);
        }
        if (lane == 0) {
            float cs = dot / (fmaxf(sqrtf(na), 1e-12f) * fmaxf(sqrtf(nb), 1e-12f));
            ls += 1.0 - (double)cs;
            lc += 1.0;
        }
    }
    if (lane == 0) {
        atomicAdd(&g_acc[accOff], ls);
        if (useMask) atomicAdd(&g_acc[accOff + 1], lc);
    }
}

__global__ void k_finalize(float* out) {
    double v = g_acc[0] / g_acc[1] + g_acc[2] / g_acc[3] + 0.1 * (g_acc[4] / (double)NN);
    out[0] = (float)v;
}

// ---------------- host-side orchestration ----------------
extern "C" void kernel_launch(void* const* d_in, const int* in_sizes, int n_in,
                              void* d_out, int out_size) {
    const float* x   = (const float*)d_in[0];
    const void*  ei1 = d_in[1];
    const void*  ei2 = d_in[2];
    const void*  m1  = d_in[3];
    const void*  m2  = d_in[4];
    const float* e0_w1 = (const float*)d_in[6];
    const float* e0_w2 = (const float*)d_in[7];
    const float* e0_bg = (const float*)d_in[8];
    const float* e0_bb = (const float*)d_in[9];
    const float* e0_ng = (const float*)d_in[10];
    const float* e0_nb = (const float*)d_in[11];
    const float* e1_w1 = (const float*)d_in[12];
    const float* e1_w2 = (const float*)d_in[13];
    const float* e1_bg = (const float*)d_in[14];
    const float* e1_bb = (const float*)d_in[15];
    const float* e1_ng = (const float*)d_in[16];
    const float* e1_nb = (const float*)d_in[17];
    const float* d_w1  = (const float*)d_in[18];
    const float* d_w2  = (const float*)d_in[19];
    const float* d_bg  = (const float*)d_in[20];
    const float* d_bb  = (const float*)d_in[21];
    const float* d_ng  = (const float*)d_in[22];
    const float* d_nb  = (const float*)d_in[23];
    float* out = (float*)d_out;

    __nv_bfloat16 *Hb, *Tb, *WTb;
    float *U, *RE1, *RE2;
    cudaGetSymbolAddress((void**)&Hb,  g_Hb);
    cudaGetSymbolAddress((void**)&Tb,  g_Tb);
    cudaGetSymbolAddress((void**)&WTb, g_WTb);
    cudaGetSymbolAddress((void**)&U,   g_U);
    cudaGetSymbolAddress((void**)&RE1, g_RE1);
    cudaGetSymbolAddress((void**)&RE2, g_RE2);

    __nv_bfloat16* WT0 = WTb;            // e0_w1: [512][128]
    __nv_bfloat16* WT1 = WTb + 65536;    // e0_w2: [256][512]
    __nv_bfloat16* WT2 = WTb + 196608;   // e1_w1: [512][256]
    __nv_bfloat16* WT3 = WTb + 327680;   // e1_w2: [256][512]
    __nv_bfloat16* WT4 = WTb + 458752;   // d_w1 : [512][256]
    __nv_bfloat16* WT5 = WTb + 589824;   // d_w2 : [128][512]

    k_zero_cnt<<<1, 32>>>();
    k_detect<<<128, 256>>>((const unsigned char*)m1, (const int*)ei1);
    k_detect_fin<<<1, 32>>>();
    k_zero_acc<<<2, 256>>>();

    dim3 tb(32, 8);
    k_transpose<<<dim3(512/32, 128/32), tb>>>(e0_w1, WT0, 128, 512);
    k_transpose<<<dim3(256/32, 512/32), tb>>>(e0_w2, WT1, 512, 256);
    k_transpose<<<dim3(512/32, 256/32), tb>>>(e1_w1, WT2, 256, 512);
    k_transpose<<<dim3(256/32, 512/32), tb>>>(e1_w2, WT3, 512, 256);
    k_transpose<<<dim3(512/32, 256/32), tb>>>(d_w1,  WT4, 256, 512);
    k_transpose<<<dim3(128/32, 512/32), tb>>>(d_w2,  WT5, 512, 128);

    const int AGG_BLK = (NN * 32 + 255) / 256;
    const dim3 gN512(4, MPAD / 128);
    const dim3 gN256(2, MPAD / 128);
    const dim3 gN128(1, MPAD / 128);

    for (int pass = 0; pass < 2; pass++) {
        const void* ei = pass == 0 ? ei1 : ei2;
        const void* m  = pass == 0 ? m1  : m2;
        float*      RE = pass == 0 ? RE1 : RE2;

        k_zero_deg<<<256, 256>>>();
        k_count<<<1024, 256>>>(ei);
        k_scan<<<1, 1024>>>();
        k_fill<<<1024, 256>>>(ei);

        // ---- encoder layer 0 ----
        k_aggregate<128, true, false><<<AGG_BLK, 256>>>(x, Hb, m, nullptr, nullptr);
        k_gemm<true><<<gN512, 256>>>(Hb, WT0, nullptr, Tb, NN, 128, 512);
        k_bn_fin<<<1, 512>>>(512);
        k_bnrelu_b<<<8192, 256>>>((__nv_bfloat162*)Tb, e0_bg, e0_bb, 255, (long)NN * 256);
        k_gemm<false><<<gN256, 256>>>(Tb, WT1, U, nullptr, NN, 512, 256);
        k_bn_fin<<<1, 512>>>(256);

        // ---- encoder layer 1 ----
        k_aggregate<256, false, true><<<AGG_BLK, 256>>>(U, Hb, nullptr, e0_ng, e0_nb);
        k_gemm<true><<<gN512, 256>>>(Hb, WT2, nullptr, Tb, NN, 256, 512);
        k_bn_fin<<<1, 512>>>(512);
        k_bnrelu_b<<<8192, 256>>>((__nv_bfloat162*)Tb, e1_bg, e1_bb, 255, (long)NN * 256);
        k_gemm<false><<<gN256, 256>>>(Tb, WT3, U, nullptr, NN, 512, 256);
        k_bn_fin<<<1, 512>>>(256);

        // ---- decoder ----
        k_aggregate<256, true, true><<<AGG_BLK, 256>>>(U, Hb, m, e1_ng, e1_nb);
        k_gemm<true><<<gN512, 256>>>(Hb, WT4, nullptr, Tb, NN, 256, 512);
        k_bn_fin<<<1, 512>>>(512);
        k_bnrelu_b<<<8192, 256>>>((__nv_bfloat162*)Tb, d_bg, d_bb, 255, (long)NN * 256);
        k_gemm<false><<<gN128, 256>>>(Tb, WT5, U, nullptr, NN, 512, 128);
        k_bn_fin<<<1, 512>>>(128);
        k_bn_apply<<<4096, 256>>>(U, RE, d_ng, d_nb, 127, (long)NN * 128);

        k_cos<<<512, 256>>>(RE, x, m, 1, pass * 2);
    }

    k_cos<<<512, 256>>>(RE2, RE1, nullptr, 0, 4);
    k_finalize<<<1, 1>>>(out);
    (void)in_sizes; (void)n_in; (void)out_size;
}

// round 9
// speedup vs baseline: 4.0162x; 1.0054x over previous
#include <cuda_runtime.h>
#include <cuda_bf16.h>
#include <math.h>
#include <stdint.h>

#define NN    50000
#define MPAD  50048
#define NE    320000
#define D_IN  128
#define D_OUT 256
#define D_HID 512

// ---------------- scratch (static device globals; no allocation) ----------------
__device__ __nv_bfloat16 g_Hb[(size_t)MPAD * D_OUT];   // bf16 GEMM-A input (agg out)
__device__ __nv_bfloat16 g_Tb[(size_t)MPAD * D_HID];   // bf16 hidden (GEMM1 out)
__device__ __nv_bfloat16 g_Ub[(size_t)MPAD * D_OUT];   // bf16 layer output (GEMM2 out)
__device__ __nv_bfloat16 g_WTb[655360];                // bf16 transposed weights
__device__ float  g_U  [(size_t)NN * D_OUT];           // fp32 decoder pre-BN
__device__ float  g_RE1[(size_t)NN * D_IN];
__device__ float  g_RE2[(size_t)NN * D_IN];
__device__ double g_sum[D_HID];
__device__ double g_sq [D_HID];
__device__ float  g_mean[D_HID];
__device__ float  g_rstd[D_HID];
__device__ double g_acc[8];

// CSR scratch
__device__ int g_deg   [NN];
__device__ int g_rowptr[NN + 1];
__device__ int g_cursor[NN];
__device__ int g_col   [NE];

__device__ int g_mask_mode, g_ei_i64, g_cnt[8];

// ---------------- dtype detection ----------------
__global__ void k_zero_cnt() { if (threadIdx.x < 8) g_cnt[threadIdx.x] = 0; }

__global__ void k_detect(const unsigned char* __restrict__ mbytes,
                         const int* __restrict__ eints) {
    int i  = blockIdx.x * blockDim.x + threadIdx.x;
    int st = gridDim.x * blockDim.x;
    int c1 = 0, c3 = 0, ez = 0;
    for (int j = i; j < NN; j += st) {
        unsigned char v = mbytes[j];
        if (v && (j & 3) == 1) c1++;
        if (v && (j & 3) == 3) c3++;
    }
    for (int j = i; j < 100000; j += st)
        if ((j & 1) && eints[j] == 0) ez++;
    atomicAdd(&g_cnt[0], c1);
    atomicAdd(&g_cnt[1], c3);
    atomicAdd(&g_cnt[2], ez);
}

__global__ void k_detect_fin() {
    if (threadIdx.x == 0) {
        if      (g_cnt[1] > 1000) g_mask_mode = 2;
        else if (g_cnt[0] > 1000) g_mask_mode = 0;
        else                      g_mask_mode = 1;
        g_ei_i64 = (g_cnt[2] > 25000) ? 1 : 0;
    }
}

__device__ __forceinline__ bool mask_at(const void* __restrict__ m, int n) {
    int mode = g_mask_mode;
    if (mode == 0) return ((const unsigned char*)m)[n] != 0;
    if (mode == 1) return ((const int*)m)[n] != 0;
    return ((const float*)m)[n] != 0.f;
}

__device__ __forceinline__ int ei_at(const void* __restrict__ ei, long idx) {
    return g_ei_i64 ? (int)((const long long*)ei)[idx] : ((const int*)ei)[idx];
}

// ---------------- tiny utility kernels ----------------
__global__ void k_zero_acc() {
    if (threadIdx.x < 8 && blockIdx.x == 0) g_acc[threadIdx.x] = 0.0;
    int c = blockIdx.x * blockDim.x + threadIdx.x;
    if (c < D_HID) { g_sum[c] = 0.0; g_sq[c] = 0.0; }
}

// ---------------- weight transpose+convert: W[K][N] f32 -> WT[N][K] bf16 ----------------
__global__ void k_transpose(const float* __restrict__ W, __nv_bfloat16* __restrict__ WT,
                            int K, int N) {
    __shared__ float tile[32][33];
    int n0 = blockIdx.x * 32, k0 = blockIdx.y * 32;
    int tx = threadIdx.x, ty = threadIdx.y;
    #pragma unroll
    for (int i = 0; i < 4; i++)
        tile[ty + i * 8][tx] = W[(size_t)(k0 + ty + i * 8) * N + n0 + tx];
    __syncthreads();
    #pragma unroll
    for (int i = 0; i < 4; i++)
        WT[(size_t)(n0 + ty + i * 8) * K + k0 + tx] = __float2bfloat16(tile[tx][ty + i * 8]);
}

// ---------------- CSR build ----------------
__global__ void k_zero_deg() {
    int i  = blockIdx.x * blockDim.x + threadIdx.x;
    int st = gridDim.x * blockDim.x;
    for (; i < NN; i += st) g_deg[i] = 0;
}

__global__ void k_count(const void* __restrict__ ei) {
    int e  = blockIdx.x * blockDim.x + threadIdx.x;
    int st = gridDim.x * blockDim.x;
    for (; e < NE; e += st)
        atomicAdd(&g_deg[ei_at(ei, (long)NE + e)], 1);
}

__global__ void __launch_bounds__(1024) k_scan() {
    __shared__ int ssum[1024];
    const int t = threadIdx.x;
    const int C = (NN + 1023) / 1024;
    int lo = t * C, hi = min(NN, lo + C);
    int s = 0;
    for (int i = lo; i < hi; i++) s += g_deg[i];
    ssum[t] = s;
    __syncthreads();
    #pragma unroll
    for (int o = 1; o < 1024; o <<= 1) {
        int v = (t >= o) ? ssum[t - o] : 0;
        __syncthreads();
        ssum[t] += v;
        __syncthreads();
    }
    int run = (t == 0) ? 0 : ssum[t - 1];
    for (int i = lo; i < hi; i++) {
        int d = g_deg[i];
        g_rowptr[i] = run;
        g_cursor[i] = run;
        run += d;
    }
    if (t == 1023) g_rowptr[NN] = run;
}

__global__ void k_fill(const void* __restrict__ ei) {
    int e  = blockIdx.x * blockDim.x + threadIdx.x;
    int st = gridDim.x * blockDim.x;
    for (; e < NE; e += st) {
        int s = ei_at(ei, e);
        int d = ei_at(ei, (long)NE + e);
        int slot = atomicAdd(&g_cursor[d], 1);
        g_col[slot] = s;
    }
}

// ---------------- bf16 helpers ----------------
__device__ __forceinline__ uint32_t pack_bf16x2(float lo, float hi) {
    uint32_t r;
    asm("cvt.rn.bf16x2.f32 %0, %1, %2;" : "=r"(r) : "f"(hi), "f"(lo));
    return r;
}
__device__ __forceinline__ float bflo(uint32_t u) { return __uint_as_float(u << 16); }
__device__ __forceinline__ float bfhi(uint32_t u) { return __uint_as_float(u & 0xffff0000u); }

// ---- fp32-input CSR aggregate (layer 0): D=128, masked, no BN -> bf16 out ----
__global__ void k_aggregate_f(const float* __restrict__ in, __nv_bfloat16* __restrict__ hb,
                              const void* __restrict__ m) {
    const int gtid = blockIdx.x * blockDim.x + threadIdx.x;
    const int warp = gtid >> 5;
    const int lane = gtid & 31;
    if (warp >= NN) return;
    const float4* ip = (const float4*)in;

    float4 a0 = make_float4(0.f, 0.f, 0.f, 0.f);
    if (!mask_at(m, warp)) a0 = ip[(size_t)warp * 32 + lane];

    int j   = g_rowptr[warp];
    int end = g_rowptr[warp + 1];
    for (; j < end; j += 4) {
        int cnt = end - j;
        int idx[4]; bool ok[4];
        #pragma unroll
        for (int t = 0; t < 4; t++) {
            idx[t] = (t < cnt) ? __ldg(&g_col[j + t]) : 0;
            ok[t]  = (t < cnt) && !mask_at(m, idx[t]);
        }
        float4 v[4];
        #pragma unroll
        for (int t = 0; t < 4; t++)
            if (ok[t]) v[t] = __ldg(&ip[(size_t)idx[t] * 32 + lane]);
        #pragma unroll
        for (int t = 0; t < 4; t++)
            if (ok[t]) { a0.x += v[t].x; a0.y += v[t].y; a0.z += v[t].z; a0.w += v[t].w; }
    }
    uint2* hp = (uint2*)hb;
    hp[(size_t)warp * 32 + lane] = make_uint2(pack_bf16x2(a0.x, a0.y), pack_bf16x2(a0.z, a0.w));
}

// ---- bf16-input CSR aggregate: D=256, fused BN+ReLU, optional mask -> bf16 out ----
// lane covers 8 contiguous channels (lane*8 .. lane*8+7): one uint4 per row.
template <bool MASKED>
__global__ void k_aggregate_b(const __nv_bfloat16* __restrict__ in, __nv_bfloat16* __restrict__ hb,
                              const void* __restrict__ m,
                              const float* __restrict__ gg, const float* __restrict__ bb) {
    const int gtid = blockIdx.x * blockDim.x + threadIdx.x;
    const int warp = gtid >> 5;
    const int lane = gtid & 31;
    if (warp >= NN) return;
    const uint4* ip = (const uint4*)in;   // 8 bf16 per uint4; 32 lanes = 256 cols

    float sc[8], sh[8];
    #pragma unroll
    for (int i = 0; i < 8; i++) {
        int ch = lane * 8 + i;
        sc[i] = g_rstd[ch] * __ldg(&gg[ch]);
        sh[i] = __ldg(&bb[ch]) - g_mean[ch] * sc[i];
    }

    float a[8];
    #pragma unroll
    for (int i = 0; i < 8; i++) a[i] = 0.f;

    auto consume = [&](uint4 u) {
        float f[8];
        f[0] = bflo(u.x); f[1] = bfhi(u.x);
        f[2] = bflo(u.y); f[3] = bfhi(u.y);
        f[4] = bflo(u.z); f[5] = bfhi(u.z);
        f[6] = bflo(u.w); f[7] = bfhi(u.w);
        #pragma unroll
        for (int i = 0; i < 8; i++)
            a[i] += fmaxf(f[i] * sc[i] + sh[i], 0.f);
    };

    if (!(MASKED && mask_at(m, warp)))
        consume(ip[(size_t)warp * 32 + lane]);

    int j   = g_rowptr[warp];
    int end = g_rowptr[warp + 1];
    for (; j < end; j += 4) {
        int cnt = end - j;
        int idx[4]; bool ok[4];
        #pragma unroll
        for (int t = 0; t < 4; t++) {
            idx[t] = (t < cnt) ? __ldg(&g_col[j + t]) : 0;
            ok[t]  = (t < cnt) && (!MASKED || !mask_at(m, idx[t]));
        }
        uint4 v[4];
        #pragma unroll
        for (int t = 0; t < 4; t++)
            if (ok[t]) v[t] = __ldg(&ip[(size_t)idx[t] * 32 + lane]);
        #pragma unroll
        for (int t = 0; t < 4; t++)
            if (ok[t]) consume(v[t]);
    }

    uint4* hp = (uint4*)hb;
    hp[(size_t)warp * 32 + lane] = make_uint4(
        pack_bf16x2(a[0], a[1]), pack_bf16x2(a[2], a[3]),
        pack_bf16x2(a[4], a[5]), pack_bf16x2(a[6], a[7]));
}

// ---------------- cp.async helpers ----------------
__device__ __forceinline__ void cp_async16(uint32_t dst, const void* src) {
    asm volatile("cp.async.cg.shared.global [%0], [%1], 16;" :: "r"(dst), "l"(src));
}
__device__ __forceinline__ void cp_commit() { asm volatile("cp.async.commit_group;"); }
template <int W> __device__ __forceinline__ void cp_wait() {
    asm volatile("cp.async.wait_group %0;" :: "n"(W));
}

// ---------------- bf16 mma ----------------
__device__ __forceinline__ void mma_bf16(float* d, const uint32_t* a, const uint32_t* b) {
    asm volatile(
        "mma.sync.aligned.m16n8k16.row.col.f32.bf16.bf16.f32 "
        "{%0,%1,%2,%3}, {%4,%5,%6,%7}, {%8,%9}, {%0,%1,%2,%3};"
        : "+f"(d[0]), "+f"(d[1]), "+f"(d[2]), "+f"(d[3])
        : "r"(a[0]), "r"(a[1]), "r"(a[2]), "r"(a[3]), "r"(b[0]), "r"(b[1]));
}

// ---------------- 3-stage pipelined bf16 GEMM ----------------
// C = A[MPADxK]bf16 @ Bt[NxK]bf16^T; epilogue: per-col sum/sumsq -> g_sum/g_sq.
#define SW 20
#define BUFW (128 * SW)                 // words per matrix per stage
#define GEMM_DSMEM (3 * 2 * BUFW * 4)   // 61440 bytes

template <bool WBF16>
__global__ void __launch_bounds__(256)
k_gemm(const __nv_bfloat16* __restrict__ A, const __nv_bfloat16* __restrict__ Bt,
       float* __restrict__ C, __nv_bfloat16* __restrict__ Cb,
       int M, int K, int N) {
    extern __shared__ uint32_t dsm[];
    const uint32_t sbase = (uint32_t)__cvta_generic_to_shared(dsm);

    const int tid  = threadIdx.x;
    const int lane = tid & 31;
    const int warp = tid >> 5;
    const int wm   = warp & 3;
    const int wn   = warp >> 2;
    const int gid  = lane >> 2;
    const int tq   = lane & 3;
    const int brow = blockIdx.y * 128;
    const int bcol = blockIdx.x * 128;

    float acc[2][8][4];
    #pragma unroll
    for (int i = 0; i < 2; i++)
        #pragma unroll
        for (int j = 0; j < 8; j++)
            #pragma unroll
            for (int q = 0; q < 4; q++) acc[i][j][q] = 0.f;

    const int nch = K >> 5;

    auto fill = [&](int s, int k0) {
        uint32_t abase = sbase + (uint32_t)(s * 2 * BUFW) * 4;
        uint32_t bbase = abase + (uint32_t)BUFW * 4;
        #pragma unroll
        for (int i = 0; i < 2; i++) {
            int idx = tid + i * 256;
            int row = idx >> 2;
            int c16 = idx & 3;
            uint32_t doff = (uint32_t)(row * SW + c16 * 4) * 4;
            cp_async16(abase + doff, A  + (size_t)(brow + row) * K + k0 + c16 * 8);
            cp_async16(bbase + doff, Bt + (size_t)(bcol + row) * K + k0 + c16 * 8);
        }
    };

    fill(0, 0);  cp_commit();
    fill(1, 32); cp_commit();

    for (int c = 0; c < nch; c++) {
        if (c < nch - 1) cp_wait<1>(); else cp_wait<0>();
        __syncthreads();
        if (c + 2 < nch) { fill((c + 2) % 3, (c + 2) << 5); cp_commit(); }

        const uint32_t* As = dsm + (c % 3) * 2 * BUFW;
        const uint32_t* Bs = As + BUFW;
        #pragma unroll
        for (int kw = 0; kw < 16; kw += 8) {
            uint32_t a[2][4], b[8][2];
            #pragma unroll
            for (int mt = 0; mt < 2; mt++) {
                int r = wm * 32 + mt * 16 + gid;
                a[mt][0] = As[r * SW + kw + tq];
                a[mt][1] = As[(r + 8) * SW + kw + tq];
                a[mt][2] = As[r * SW + kw + tq + 4];
                a[mt][3] = As[(r + 8) * SW + kw + tq + 4];
            }
            #pragma unroll
            for (int nt = 0; nt < 8; nt++) {
                int cn = wn * 64 + nt * 8 + gid;
                b[nt][0] = Bs[cn * SW + kw + tq];
                b[nt][1] = Bs[cn * SW + kw + tq + 4];
            }
            #pragma unroll
            for (int mt = 0; mt < 2; mt++)
                #pragma unroll
                for (int nt = 0; nt < 8; nt++)
                    mma_bf16(acc[mt][nt], a[mt], b[nt]);
        }
        __syncthreads();
    }

    // ---- store C ----
    #pragma unroll
    for (int mt = 0; mt < 2; mt++) {
        int r0 = brow + wm * 32 + mt * 16 + gid;
        int r1 = r0 + 8;
        #pragma unroll
        for (int nt = 0; nt < 8; nt++) {
            int c = bcol + wn * 64 + nt * 8 + tq * 2;
            if (WBF16) {
                if (r0 < M)
                    *(uint32_t*)(Cb + (size_t)r0 * N + c) = pack_bf16x2(acc[mt][nt][0], acc[mt][nt][1]);
                if (r1 < M)
                    *(uint32_t*)(Cb + (size_t)r1 * N + c) = pack_bf16x2(acc[mt][nt][2], acc[mt][nt][3]);
            } else {
                if (r0 < M)
                    *(float2*)(C + (size_t)r0 * N + c) = make_float2(acc[mt][nt][0], acc[mt][nt][1]);
                if (r1 < M)
                    *(float2*)(C + (size_t)r1 * N + c) = make_float2(acc[mt][nt][2], acc[mt][nt][3]);
            }
        }
    }

    // ---- column stats (reuse pipeline smem) ----
    float csum[16], csq[16];
    #pragma unroll
    for (int nt = 0; nt < 8; nt++) {
        float s0 = 0.f, s1 = 0.f, q0 = 0.f, q1 = 0.f;
        #pragma unroll
        for (int mt = 0; mt < 2; mt++) {
            int r0 = brow + wm * 32 + mt * 16 + gid;
            int r1 = r0 + 8;
            if (r0 < M) {
                float a = acc[mt][nt][0], b = acc[mt][nt][1];
                s0 += a; q0 += a * a; s1 += b; q1 += b * b;
            }
            if (r1 < M) {
                float a = acc[mt][nt][2], b = acc[mt][nt][3];
                s0 += a; q0 += a * a; s1 += b; q1 += b * b;
            }
        }
        csum[nt * 2] = s0; csum[nt * 2 + 1] = s1;
        csq [nt * 2] = q0; csq [nt * 2 + 1] = q1;
    }
    #pragma unroll
    for (int o = 4; o <= 16; o <<= 1) {
        #pragma unroll
        for (int p = 0; p < 16; p++) {
            csum[p] += __shfl_xor_sync(0xffffffffu, csum[p], o);
            csq[p]  += __shfl_xor_sync(0xffffffffu, csq[p],  o);
        }
    }
    float* s_ps = (float*)dsm;          // [4][128]
    float* s_pq = s_ps + 512;           // [4][128]
    __syncthreads();
    if (gid == 0) {
        #pragma unroll
        for (int nt = 0; nt < 8; nt++) {
            int lc = wn * 64 + nt * 8 + tq * 2;
            s_ps[wm * 128 + lc]     = csum[nt * 2];
            s_ps[wm * 128 + lc + 1] = csum[nt * 2 + 1];
            s_pq[wm * 128 + lc]     = csq[nt * 2];
            s_pq[wm * 128 + lc + 1] = csq[nt * 2 + 1];
        }
    }
    __syncthreads();
    if (tid < 128) {
        float ts = s_ps[tid] + s_ps[128 + tid] + s_ps[256 + tid] + s_ps[384 + tid];
        float tg = s_pq[tid] + s_pq[128 + tid] + s_pq[256 + tid] + s_pq[384 + tid];
        atomicAdd(&g_sum[bcol + tid], (double)ts);
        atomicAdd(&g_sq[bcol + tid],  (double)tg);
    }
}

__global__ void k_bn_fin(int C) {
    int c = threadIdx.x;
    if (c < C) {
        double mu  = g_sum[c] / NN;
        double var = g_sq[c] / NN - mu * mu;
        if (var < 0.0) var = 0.0;
        g_mean[c] = (float)mu;
        g_rstd[c] = (float)rsqrt(var + 1e-5);
    }
    if (c < D_HID) { g_sum[c] = 0.0; g_sq[c] = 0.0; }
}

// in-place bf16 BN+ReLU over Tb
__global__ void k_bnrelu_b(__nv_bfloat162* __restrict__ t,
                           const float* __restrict__ gg, const float* __restrict__ bb,
                           int cpmask, long totalPairs) {
    long i  = blockIdx.x * (long)blockDim.x + threadIdx.x;
    long st = (long)gridDim.x * blockDim.x;
    for (; i < totalPairs; i += st) {
        int c = (int)(i & cpmask) * 2;
        float sx = g_rstd[c]     * __ldg(&gg[c]);
        float sy = g_rstd[c + 1] * __ldg(&gg[c + 1]);
        float tx = __ldg(&bb[c])     - g_mean[c]     * sx;
        float ty = __ldg(&bb[c + 1]) - g_mean[c + 1] * sy;
        __nv_bfloat162 v = t[i];
        float a = fmaxf(__bfloat162float(v.x) * sx + tx, 0.f);
        float b = fmaxf(__bfloat162float(v.y) * sy + ty, 0.f);
        uint32_t p = pack_bf16x2(a, b);
        t[i] = *(__nv_bfloat162*)&p;
    }
}

// fp32 BN+ReLU (decoder output)
__global__ void k_bn_apply(const float* __restrict__ in, float* __restrict__ out,
                           const float* __restrict__ gg, const float* __restrict__ bb,
                           int cmask, long total) {
    long i  = blockIdx.x * (long)blockDim.x + threadIdx.x;
    long st = (long)gridDim.x * blockDim.x;
    for (; i < total; i += st) {
        int c   = (int)(i & cmask);
        float v = (in[i] - g_mean[c]) * g_rstd[c] * __ldg(&gg[c]) + __ldg(&bb[c]);
        out[i] = v > 0.f ? v : 0.f;
    }
}

// ---------------- cosine losses ----------------
__global__ void k_cos(const float* __restrict__ a, const float* __restrict__ b,
                      const void* __restrict__ m, int useMask, int accOff) {
    int gtid = blockIdx.x * blockDim.x + threadIdx.x;
    int warp = gtid >> 5, lane = gtid & 31;
    int nw   = (gridDim.x * blockDim.x) >> 5;
    double ls = 0.0, lc = 0.0;
    for (int n = warp; n < NN; n += nw) {
        if (useMask && !mask_at(m, n)) continue;
        float4 va = *((const float4*)(a + (size_t)n * 128) + lane);
        float4 vb = *((const float4*)(b + (size_t)n * 128) + lane);
        float dot = va.x * vb.x + va.y * vb.y + va.z * vb.z + va.w * vb.w;
        float na  = va.x * va.x + va.y * va.y + va.z * va.z + va.w * va.w;
        float nb  = vb.x * vb.x + vb.y * vb.y + vb.z * vb.z + vb.w * vb.w;
        #pragma unroll
        for (int o = 16; o; o >>= 1) {
            dot += __shfl_xor_sync(0xffffffffu, dot, o);
            na  += __shfl_xor_sync(0xffffffffu, na,  o);
            nb  += __shfl_xor_sync(0xffffffffu, nb,  o);
        }
        if (lane == 0) {
            float cs = dot / (fmaxf(sqrtf(na), 1e-12f) * fmaxf(sqrtf(nb), 1e-12f));
            ls += 1.0 - (double)cs;
            lc += 1.0;
        }
    }
    if (lane == 0) {
        atomicAdd(&g_acc[accOff], ls);
        if (useMask) atomicAdd(&g_acc[accOff + 1], lc);
    }
}

__global__ void k_finalize(float* out) {
    double v = g_acc[0] / g_acc[1] + g_acc[2] / g_acc[3] + 0.1 * (g_acc[4] / (double)NN);
    out[0] = (float)v;
}

// ---------------- host-side orchestration ----------------
extern "C" void kernel_launch(void* const* d_in, const int* in_sizes, int n_in,
                              void* d_out, int out_size) {
    const float* x   = (const float*)d_in[0];
    const void*  ei1 = d_in[1];
    const void*  ei2 = d_in[2];
    const void*  m1  = d_in[3];
    const void*  m2  = d_in[4];
    const float* e0_w1 = (const float*)d_in[6];
    const float* e0_w2 = (const float*)d_in[7];
    const float* e0_bg = (const float*)d_in[8];
    const float* e0_bb = (const float*)d_in[9];
    const float* e0_ng = (const float*)d_in[10];
    const float* e0_nb = (const float*)d_in[11];
    const float* e1_w1 = (const float*)d_in[12];
    const float* e1_w2 = (const float*)d_in[13];
    const float* e1_bg = (const float*)d_in[14];
    const float* e1_bb = (const float*)d_in[15];
    const float* e1_ng = (const float*)d_in[16];
    const float* e1_nb = (const float*)d_in[17];
    const float* d_w1  = (const float*)d_in[18];
    const float* d_w2  = (const float*)d_in[19];
    const float* d_bg  = (const float*)d_in[20];
    const float* d_bb  = (const float*)d_in[21];
    const float* d_ng  = (const float*)d_in[22];
    const float* d_nb  = (const float*)d_in[23];
    float* out = (float*)d_out;

    __nv_bfloat16 *Hb, *Tb, *Ub, *WTb;
    float *U, *RE1, *RE2;
    cudaGetSymbolAddress((void**)&Hb,  g_Hb);
    cudaGetSymbolAddress((void**)&Tb,  g_Tb);
    cudaGetSymbolAddress((void**)&Ub,  g_Ub);
    cudaGetSymbolAddress((void**)&WTb, g_WTb);
    cudaGetSymbolAddress((void**)&U,   g_U);
    cudaGetSymbolAddress((void**)&RE1, g_RE1);
    cudaGetSymbolAddress((void**)&RE2, g_RE2);

    __nv_bfloat16* WT0 = WTb;            // e0_w1: [512][128]
    __nv_bfloat16* WT1 = WTb + 65536;    // e0_w2: [256][512]
    __nv_bfloat16* WT2 = WTb + 196608;   // e1_w1: [512][256]
    __nv_bfloat16* WT3 = WTb + 327680;   // e1_w2: [256][512]
    __nv_bfloat16* WT4 = WTb + 458752;   // d_w1 : [512][256]
    __nv_bfloat16* WT5 = WTb + 589824;   // d_w2 : [128][512]

    cudaFuncSetAttribute(k_gemm<true>,  cudaFuncAttributeMaxDynamicSharedMemorySize, GEMM_DSMEM);
    cudaFuncSetAttribute(k_gemm<false>, cudaFuncAttributeMaxDynamicSharedMemorySize, GEMM_DSMEM);

    k_zero_cnt<<<1, 32>>>();
    k_detect<<<128, 256>>>((const unsigned char*)m1, (const int*)ei1);
    k_detect_fin<<<1, 32>>>();
    k_zero_acc<<<2, 256>>>();

    dim3 tb(32, 8);
    k_transpose<<<dim3(512/32, 128/32), tb>>>(e0_w1, WT0, 128, 512);
    k_transpose<<<dim3(256/32, 512/32), tb>>>(e0_w2, WT1, 512, 256);
    k_transpose<<<dim3(512/32, 256/32), tb>>>(e1_w1, WT2, 256, 512);
    k_transpose<<<dim3(256/32, 512/32), tb>>>(e1_w2, WT3, 512, 256);
    k_transpose<<<dim3(512/32, 256/32), tb>>>(d_w1,  WT4, 256, 512);
    k_transpose<<<dim3(128/32, 512/32), tb>>>(d_w2,  WT5, 512, 128);

    const int AGG_BLK = (NN * 32 + 255) / 256;
    const dim3 gN512(4, MPAD / 128);
    const dim3 gN256(2, MPAD / 128);
    const dim3 gN128(1, MPAD / 128);

    for (int pass = 0; pass < 2; pass++) {
        const void* ei = pass == 0 ? ei1 : ei2;
        const void* m  = pass == 0 ? m1  : m2;
        float*      RE = pass == 0 ? RE1 : RE2;

        k_zero_deg<<<256, 256>>>();
        k_count<<<1024, 256>>>(ei);
        k_scan<<<1, 1024>>>();
        k_fill<<<1024, 256>>>(ei);

        // ---- encoder layer 0 ----
        k_aggregate_f<<<AGG_BLK, 256>>>(x, Hb, m);
        k_gemm<true><<<gN512, 256, GEMM_DSMEM>>>(Hb, WT0, nullptr, Tb, NN, 128, 512);
        k_bn_fin<<<1, 512>>>(512);
        k_bnrelu_b<<<8192, 256>>>((__nv_bfloat162*)Tb, e0_bg, e0_bb, 255, (long)NN * 256);
        k_gemm<true><<<gN256, 256, GEMM_DSMEM>>>(Tb, WT1, nullptr, Ub, NN, 512, 256);
        k_bn_fin<<<1, 512>>>(256);

        // ---- encoder layer 1 (BN+ReLU fused into bf16 gather) ----
        k_aggregate_b<false><<<AGG_BLK, 256>>>(Ub, Hb, nullptr, e0_ng, e0_nb);
        k_gemm<true><<<gN512, 256, GEMM_DSMEM>>>(Hb, WT2, nullptr, Tb, NN, 256, 512);
        k_bn_fin<<<1, 512>>>(512);
        k_bnrelu_b<<<8192, 256>>>((__nv_bfloat162*)Tb, e1_bg, e1_bb, 255, (long)NN * 256);
        k_gemm<true><<<gN256, 256, GEMM_DSMEM>>>(Tb, WT3, nullptr, Ub, NN, 512, 256);
        k_bn_fin<<<1, 512>>>(256);

        // ---- decoder ----
        k_aggregate_b<true><<<AGG_BLK, 256>>>(Ub, Hb, m, e1_ng, e1_nb);
        k_gemm<true><<<gN512, 256, GEMM_DSMEM>>>(Hb, WT4, nullptr, Tb, NN, 256, 512);
        k_bn_fin<<<1, 512>>>(512);
        k_bnrelu_b<<<8192, 256>>>((__nv_bfloat162*)Tb, d_bg, d_bb, 255, (long)NN * 256);
        k_gemm<false><<<gN128, 256, GEMM_DSMEM>>>(Tb, WT5, U, nullptr, NN, 512, 128);
        k_bn_fin<<<1, 512>>>(128);
        k_bn_apply<<<4096, 256>>>(U, RE, d_ng, d_nb, 127, (long)NN * 128);

        k_cos<<<512, 256>>>(RE, x, m, 1, pass * 2);
    }

    k_cos<<<512, 256>>>(RE2, RE1, nullptr, 0, 4);
    k_finalize<<<1, 1>>>(out);
    (void)in_sizes; (void)n_in; (void)out_size;
}